// round 10
// baseline (speedup 1.0000x reference)
#include <cuda_runtime.h>
#include <cuda_bf16.h>
#include <math.h>

// Problem constants
#define CB    2
#define CN    1024
#define CPAST 1024
#define CKV   2048
#define CDIM  2048
#define CH    16
#define CDH   128
#define NTOK  2048            // CB*CN
#define NQKV  6144            // 3*HEADS*DH
#define SCALE 0.08838834764831845f   // 128^-0.5

// ---------------- scratch (device globals; no dynamic alloc allowed) -------
__device__ float g_q[CB * CH * CN * CDH];    // raw q from gemm [b,h,n,d]
__device__ float g_cos[CKV * 64];
__device__ float g_sin[CKV * 64];
__device__ unsigned short g_xn_hi[NTOK * CDIM];
__device__ unsigned short g_xn_lo[NTOK * CDIM];
__device__ unsigned short g_attn_hi[NTOK * CDIM];
__device__ unsigned short g_attn_lo[NTOK * CDIM];
__device__ unsigned short g_wqkvT_hi[NQKV * CDIM];   // [n][k]
__device__ unsigned short g_wqkvT_lo[NQKV * CDIM];
__device__ unsigned short g_woutT_hi[CDIM * CDIM];   // [n][k]
__device__ unsigned short g_woutT_lo[CDIM * CDIM];
// pre-split attention operands
__device__ unsigned short g_q_hi[CB * CH * CN * CDH];
__device__ unsigned short g_q_lo[CB * CH * CN * CDH];
__device__ unsigned short g_k_hi[CB * CH * CKV * CDH];
__device__ unsigned short g_k_lo[CB * CH * CKV * CDH];
__device__ unsigned short g_v_hi[CB * CH * CKV * CDH];
__device__ unsigned short g_v_lo[CB * CH * CKV * CDH];

extern __shared__ char smem[];

// ---------------- small helpers --------------------------------------------
__device__ __forceinline__ unsigned smem_u32(const void* p) {
    unsigned a;
    asm("{ .reg .u64 t; cvta.to.shared.u64 t, %1; cvt.u32.u64 %0, t; }"
        : "=r"(a) : "l"(p));
    return a;
}

__device__ __forceinline__ void bf16_split(float v, unsigned short& h, unsigned short& l) {
    __nv_bfloat16 bh = __float2bfloat16(v);
    float r = v - __bfloat162float(bh);
    __nv_bfloat16 bl = __float2bfloat16(r);
    h = __bfloat16_as_ushort(bh);
    l = __bfloat16_as_ushort(bl);
}

__device__ __forceinline__ void split2(float a, float b, unsigned& h, unsigned& l) {
    __nv_bfloat16 ah = __float2bfloat16(a), bh_ = __float2bfloat16(b);
    float ar = a - __bfloat162float(ah), br = b - __bfloat162float(bh_);
    __nv_bfloat16 al = __float2bfloat16(ar), bl = __float2bfloat16(br);
    h = (unsigned)__bfloat16_as_ushort(ah) | ((unsigned)__bfloat16_as_ushort(bh_) << 16);
    l = (unsigned)__bfloat16_as_ushort(al) | ((unsigned)__bfloat16_as_ushort(bl) << 16);
}

__device__ __forceinline__ void cp16(unsigned dst, const void* src) {
    asm volatile("cp.async.cg.shared.global [%0], [%1], 16;" :: "r"(dst), "l"(src));
}

__device__ __forceinline__ void ldsm_x4(unsigned* r, unsigned addr) {
    asm volatile("ldmatrix.sync.aligned.m8n8.x4.shared.b16 {%0,%1,%2,%3}, [%4];"
                 : "=r"(r[0]), "=r"(r[1]), "=r"(r[2]), "=r"(r[3]) : "r"(addr));
}

__device__ __forceinline__ void ldsm_x4t(unsigned* r, unsigned addr) {
    asm volatile("ldmatrix.sync.aligned.m8n8.x4.trans.shared.b16 {%0,%1,%2,%3}, [%4];"
                 : "=r"(r[0]), "=r"(r[1]), "=r"(r[2]), "=r"(r[3]) : "r"(addr));
}

__device__ __forceinline__ void mma_bf16(float* c, const unsigned* a, const unsigned* b) {
    asm volatile(
        "mma.sync.aligned.m16n8k16.row.col.f32.bf16.bf16.f32 "
        "{%0,%1,%2,%3}, {%4,%5,%6,%7}, {%8,%9}, {%0,%1,%2,%3};"
        : "+f"(c[0]), "+f"(c[1]), "+f"(c[2]), "+f"(c[3])
        : "r"(a[0]), "r"(a[1]), "r"(a[2]), "r"(a[3]), "r"(b[0]), "r"(b[1]));
}

// ---------------- RoPE table (f32 angles to match JAX; DP range reduce) ----
__global__ void rope_table_kernel() {
    int idx = blockIdx.x * blockDim.x + threadIdx.x;
    if (idx >= CKV * 64) return;
    int pos = idx >> 6, i = idx & 63;
    float w = powf(10000.0f, -((float)i) / 64.0f);
    float ang = (float)pos * w;
    double d = (double)ang;
    double q = rint(d * 0.15915494309189535);   // 1/(2*pi)
    float r = (float)(d - q * 6.283185307179586);
    g_cos[idx] = cosf(r);
    g_sin[idx] = sinf(r);
}

// ---------------- LayerNorm -> bf16 hi/lo ----------------------------------
__global__ void ln_kernel(const float* __restrict__ x,
                          const float* __restrict__ gam,
                          const float* __restrict__ bet) {
    int row = blockIdx.x;
    int tid = threadIdx.x;
    const float* xp = x + (size_t)row * CDIM;

    float4 v1 = *(const float4*)(xp + tid * 8);
    float4 v2 = *(const float4*)(xp + tid * 8 + 4);
    float vals[8] = {v1.x, v1.y, v1.z, v1.w, v2.x, v2.y, v2.z, v2.w};
    float s = 0.f, ss = 0.f;
#pragma unroll
    for (int i = 0; i < 8; i++) { s += vals[i]; ss += vals[i] * vals[i]; }
#pragma unroll
    for (int o = 16; o; o >>= 1) {
        s  += __shfl_xor_sync(0xffffffffu, s, o);
        ss += __shfl_xor_sync(0xffffffffu, ss, o);
    }
    __shared__ float sh_s[8], sh_ss[8];
    __shared__ float sh_mu, sh_rstd;
    int wid = tid >> 5, lane = tid & 31;
    if (lane == 0) { sh_s[wid] = s; sh_ss[wid] = ss; }
    __syncthreads();
    if (tid == 0) {
        float S = 0.f, SS = 0.f;
#pragma unroll
        for (int i = 0; i < 8; i++) { S += sh_s[i]; SS += sh_ss[i]; }
        float mu = S / (float)CDIM;
        float var = SS / (float)CDIM - mu * mu;
        sh_mu = mu;
        sh_rstd = rsqrtf(var + 1e-5f);
    }
    __syncthreads();
    float mu = sh_mu, rstd = sh_rstd;
#pragma unroll
    for (int i = 0; i < 8; i++) {
        int c = tid * 8 + i;
        float v = (vals[i] - mu) * rstd * gam[c] + bet[c];
        unsigned short h, l;
        bf16_split(v, h, l);
        size_t o = (size_t)row * CDIM + c;
        g_xn_hi[o] = h;
        g_xn_lo[o] = l;
    }
}

// ---------------- transpose + bf16 split weights ---------------------------
template <int WSEL>
__global__ void transpose_split_kernel(const float* __restrict__ w) {
    constexpr int N = (WSEL == 0) ? NQKV : CDIM;
    unsigned short* hi = (WSEL == 0) ? g_wqkvT_hi : g_woutT_hi;
    unsigned short* lo = (WSEL == 0) ? g_wqkvT_lo : g_woutT_lo;
    __shared__ float t[32][33];
    int n0 = blockIdx.x * 32, k0 = blockIdx.y * 32;
    int tx = threadIdx.x, ty = threadIdx.y;
#pragma unroll
    for (int i = ty; i < 32; i += 8)
        t[i][tx] = w[(size_t)(k0 + i) * N + n0 + tx];
    __syncthreads();
#pragma unroll
    for (int i = ty; i < 32; i += 8) {
        float v = t[tx][i];
        size_t o = (size_t)(n0 + i) * CDIM + k0 + tx;
        unsigned short h, l;
        bf16_split(v, h, l);
        hi[o] = h;
        lo[o] = l;
    }
}

// ---------------- mma.sync 3xBF16 GEMM: CTA 128x256, warp 64x64, occ 1 -----
// Crossbar math: warp reads (64+64)*32*4 B per chunk for 192 MMAs ->
// ~85 B/cyc/SM demand + writes 48KB/chunk -> below 128 B/cyc crossbar.
#define KC        32
#define MAT_A     10240              // 128 rows * 80 B
#define MAT_B     20480              // 256 rows * 80 B
#define BUF_G     61440              // Ah,Al,Bh,Bl per stage
#define SMEM_G    (2 * BUF_G)        // 122880 B

template <int NTOT, int MODE>
__global__ __launch_bounds__(256, 1)
void mma_gemm(float* __restrict__ C, float* __restrict__ kout,
              float* __restrict__ vout) {
    const unsigned short* Ah_g = (MODE == 1) ? g_xn_hi : g_attn_hi;
    const unsigned short* Al_g = (MODE == 1) ? g_xn_lo : g_attn_lo;
    const unsigned short* Bh_g = (MODE == 1) ? g_wqkvT_hi : g_woutT_hi;
    const unsigned short* Bl_g = (MODE == 1) ? g_wqkvT_lo : g_woutT_lo;

    unsigned sb = smem_u32(smem);
    int tid = threadIdx.x, warp = tid >> 5, lane = tid & 31;
    int bm = blockIdx.y, bn = blockIdx.x;
    int wm = warp & 1, wn = warp >> 1;          // 2 x 4 warp grid, 64x64 tiles

    float acc[4][8][4];
#pragma unroll
    for (int i = 0; i < 4; i++)
#pragma unroll
        for (int j = 0; j < 8; j++)
#pragma unroll
            for (int k = 0; k < 4; k++) acc[i][j][k] = 0.f;

    // 3072 cp16 slots per chunk: A hi 0..511, A lo 512..1023,
    // B hi 1024..2047, B lo 2048..3071; 12 per thread.
#define LOAD_CHUNK(cc, st)                                                     \
    {                                                                          \
        int k0 = (cc) * KC;                                                    \
        unsigned bufa = sb + (st) * BUF_G;                                     \
        _Pragma("unroll")                                                      \
        for (int it = 0; it < 12; it++) {                                      \
            int s = tid + it * 256;                                            \
            if (s < 1024) {                                                    \
                int mat = s >> 9, r = (s >> 2) & 127, g = s & 3;               \
                size_t gi = (size_t)(bm * 128 + r) * CDIM + k0 + g * 8;        \
                cp16(bufa + mat * MAT_A + r * 80 + g * 16,                     \
                     (mat ? Al_g : Ah_g) + gi);                                \
            } else {                                                           \
                int t = s - 1024;                                              \
                int mat = t >> 10, r = (t >> 2) & 255, g = t & 3;              \
                size_t gi = (size_t)(bn * 256 + r) * CDIM + k0 + g * 8;        \
                cp16(bufa + 2 * MAT_A + mat * MAT_B + r * 80 + g * 16,         \
                     (mat ? Bl_g : Bh_g) + gi);                                \
            }                                                                  \
        }                                                                      \
        asm volatile("cp.async.commit_group;");                                \
    }

    int ami = lane >> 3, ar = lane & 7;
    int a_row = (ami & 1) * 8 + ar;
    int a_col = (ami >> 1) * 8;
    int b_row = (ami >> 1) * 8 + ar;
    int b_col = (ami & 1) * 8;

    LOAD_CHUNK(0, 0);

    for (int c = 0; c < CDIM / KC; c++) {
        int st = c & 1;
        if (c + 1 < CDIM / KC) {
            LOAD_CHUNK(c + 1, st ^ 1);
            asm volatile("cp.async.wait_group 1;");
        } else {
            asm volatile("cp.async.wait_group 0;");
        }
        __syncthreads();

        unsigned Ab = sb + st * BUF_G;
        unsigned Bb = Ab + 2 * MAT_A;
#pragma unroll
        for (int ks = 0; ks < 2; ks++) {
            unsigned ah[4][4], al[4][4];
#pragma unroll
            for (int mt = 0; mt < 4; mt++) {
                unsigned off = (unsigned)((wm * 64 + mt * 16 + a_row) * 80
                                          + (ks * 16 + a_col) * 2);
                ldsm_x4(ah[mt], Ab + off);
                ldsm_x4(al[mt], Ab + MAT_A + off);
            }
#pragma unroll
            for (int nt2 = 0; nt2 < 4; nt2++) {
                unsigned off = (unsigned)((wn * 64 + nt2 * 16 + b_row) * 80
                                          + (ks * 16 + b_col) * 2);
                unsigned bh4[4], bl4[4];
                ldsm_x4(bh4, Bb + off);
                ldsm_x4(bl4, Bb + MAT_B + off);
                int n0i = 2 * nt2, n1i = 2 * nt2 + 1;
                // term-major, mt-major: chain distance 8 per accumulator
#pragma unroll
                for (int mt = 0; mt < 4; mt++) {
                    mma_bf16(acc[mt][n0i], ah[mt], bh4);
                    mma_bf16(acc[mt][n1i], ah[mt], bh4 + 2);
                }
#pragma unroll
                for (int mt = 0; mt < 4; mt++) {
                    mma_bf16(acc[mt][n0i], ah[mt], bl4);
                    mma_bf16(acc[mt][n1i], ah[mt], bl4 + 2);
                }
#pragma unroll
                for (int mt = 0; mt < 4; mt++) {
                    mma_bf16(acc[mt][n0i], al[mt], bh4);
                    mma_bf16(acc[mt][n1i], al[mt], bh4 + 2);
                }
            }
        }
        __syncthreads();
    }

    int crow = lane >> 2, ccol = (lane & 3) * 2;
#pragma unroll
    for (int mt = 0; mt < 4; mt++) {
#pragma unroll
        for (int nt = 0; nt < 8; nt++) {
            int gn = bn * 256 + wn * 64 + nt * 8 + ccol;
#pragma unroll
            for (int h2 = 0; h2 < 2; h2++) {
                int gm = bm * 128 + wm * 64 + mt * 16 + crow + h2 * 8;
                float2 v = make_float2(acc[mt][nt][2 * h2], acc[mt][nt][2 * h2 + 1]);
                if (MODE == 0) {
                    *(float2*)(C + (size_t)gm * NTOT + gn) = v;
                } else {
                    int sec = gn >> 11, w = gn & 2047, h = w >> 7, d0 = w & 127;
                    int b = gm >> 10, nidx = gm & 1023, bh2 = b * CH + h;
                    float* dst;
                    if (sec == 0)
                        dst = g_q + ((size_t)bh2 * CN + nidx) * CDH + d0;
                    else if (sec == 1)
                        dst = kout + ((size_t)bh2 * CKV + CPAST + nidx) * CDH + d0;
                    else
                        dst = vout + ((size_t)bh2 * CKV + CPAST + nidx) * CDH + d0;
                    *(float2*)dst = v;
                }
            }
        }
    }
#undef LOAD_CHUNK
}

// ---------------- RoPE K (full cache; also pre-split to bf16 hi/lo) --------
__global__ void rope_k_kernel(const float* __restrict__ past_k,
                              float* __restrict__ kout) {
    int idx = blockIdx.x * blockDim.x + threadIdx.x;
    if (idx >= CB * CH * CKV * 64) return;
    int i = idx & 63;
    int rest = idx >> 6;
    int p = rest & (CKV - 1);
    int bh = rest >> 11;
    float2* dst = (float2*)(kout + ((size_t)rest << 7)) + i;
    float2 xv;
    if (p < CPAST)
        xv = *((const float2*)(past_k + (((size_t)bh * CPAST + p) << 7)) + i);
    else
        xv = *dst;
    float c = g_cos[p * 64 + i], s = g_sin[p * 64 + i];
    float2 o;
    o.x = xv.x * c - xv.y * s;
    o.y = xv.y * c + xv.x * s;
    *dst = o;
    unsigned h, l;
    split2(o.x, o.y, h, l);
    ((unsigned*)g_k_hi)[((size_t)rest << 6) + i] = h;
    ((unsigned*)g_k_lo)[((size_t)rest << 6) + i] = l;
}

// ---------------- RoPE Q (scale folded; write bf16 hi/lo) ------------------
__global__ void rope_q_kernel() {
    int idx = blockIdx.x * blockDim.x + threadIdx.x;
    if (idx >= CB * CH * CN * 64) return;
    int i = idx & 63;
    int rest = idx >> 6;
    int n = rest & (CN - 1);
    int pos = CPAST + n;
    float2 xv = *((const float2*)(g_q + ((size_t)rest << 7)) + i);
    float c = g_cos[pos * 64 + i], s = g_sin[pos * 64 + i];
    float ox = (xv.x * c - xv.y * s) * SCALE;
    float oy = (xv.y * c + xv.x * s) * SCALE;
    unsigned h, l;
    split2(ox, oy, h, l);
    ((unsigned*)g_q_hi)[((size_t)rest << 6) + i] = h;
    ((unsigned*)g_q_lo)[((size_t)rest << 6) + i] = l;
}

// ---------------- V: copy past into cache + split whole cache --------------
__global__ void split_v_kernel(const float* __restrict__ past_v,
                               float* __restrict__ vout) {
    int idx = blockIdx.x * blockDim.x + threadIdx.x;
    if (idx >= CB * CH * CKV * 32) return;
    int i4 = idx & 31;
    int rest = idx >> 5;
    int p = rest & (CKV - 1);
    int bh = rest >> 11;
    float4 v;
    if (p < CPAST) {
        v = *((const float4*)past_v + (((size_t)bh * CPAST + p) << 5) + i4);
        *((float4*)vout + ((size_t)rest << 5) + i4) = v;
    } else {
        v = *((const float4*)vout + ((size_t)rest << 5) + i4);
    }
    unsigned h0, l0, h1, l1;
    split2(v.x, v.y, h0, l0);
    split2(v.z, v.w, h1, l1);
    ((uint2*)g_v_hi)[((size_t)rest << 5) + i4] = make_uint2(h0, h1);
    ((uint2*)g_v_lo)[((size_t)rest << 5) + i4] = make_uint2(l0, l1);
}

// ---------------- flash attention (mma.sync, pre-split, cp.async 2-stage) --
#define ASTRB     272
#define AQ_LO     34816
#define ST0       69632
#define STSZ      69632
#define KLOF      17408
#define VHOF      34816
#define VLOF      52224
#define SMEM_A3   208896

__global__ __launch_bounds__(256, 1) void attn_mma_kernel(
    const float* __restrict__ kc_unused, const float* __restrict__ vc_unused) {
    unsigned sb = smem_u32(smem);
    int id = blockIdx.x;
    int qt = 7 - (id & 7), bh = id >> 3;   // longest CTAs first
    int tid = threadIdx.x, warp = tid >> 5, lane = tid & 31;

    size_t qbase = ((size_t)bh * CN + qt * 128) * CDH;
    size_t kvbase = (size_t)bh * CKV * CDH;

#pragma unroll
    for (int it = 0; it < 16; it++) {
        int slot = tid + it * 256;
        int mat = slot >> 11;
        int r = (slot >> 4) & 127;
        int seg = slot & 15;
        const unsigned short* src = (mat ? g_q_lo : g_q_hi) + qbase + r * CDH + seg * 8;
        cp16(sb + mat * AQ_LO + r * ASTRB + seg * 16, src);
    }

#define LOADKV(kt_, s_)                                                         \
    {                                                                           \
        size_t tb = kvbase + (size_t)(kt_) * 64 * CDH;                          \
        _Pragma("unroll")                                                       \
        for (int it = 0; it < 16; it++) {                                      \
            int slot = tid + it * 256;                                          \
            int mat = slot >> 10;                                               \
            int r = (slot >> 4) & 63;                                           \
            int seg = slot & 15;                                                \
            const unsigned short* src =                                         \
                (mat == 0 ? g_k_hi : mat == 1 ? g_k_lo                          \
                 : mat == 2 ? g_v_hi : g_v_lo) + tb + r * CDH + seg * 8;        \
            cp16(sb + ST0 + (s_) * STSZ + mat * KLOF + r * ASTRB + seg * 16,    \
                 src);                                                          \
        }                                                                       \
        asm volatile("cp.async.commit_group;");                                 \
    }

    LOADKV(0, 0);

    float O[16][4];
#pragma unroll
    for (int i = 0; i < 16; i++)
#pragma unroll
        for (int j = 0; j < 4; j++) O[i][j] = 0.f;
    float mrow0 = -1e30f, mrow1 = -1e30f, lrow0 = 0.f, lrow1 = 0.f;

    int qpos0 = CPAST + qt * 128 + warp * 16 + (lane >> 2);
    int nkt = 18 + 2 * qt;
    int mask_start = nkt - 2;
    int mi = lane >> 3, r8 = lane & 7;

    for (int kt = 0; kt < nkt; kt++) {
        int st = kt & 1;
        if (kt + 1 < nkt) {
            LOADKV(kt + 1, st ^ 1);
            asm volatile("cp.async.wait_group 1;");
        } else {
            asm volatile("cp.async.wait_group 0;");
        }
        __syncthreads();

        unsigned kb = sb + ST0 + st * STSZ;
        unsigned vb = kb + VHOF;

        float sacc[8][4];
#pragma unroll
        for (int i = 0; i < 8; i++)
#pragma unroll
            for (int j = 0; j < 4; j++) sacc[i][j] = 0.f;

#pragma unroll
        for (int s = 0; s < 8; s++) {
            unsigned qh[4], ql[4];
            unsigned arow = warp * 16 + (mi & 1) * 8 + r8;
            unsigned ak = s * 16 + (mi >> 1) * 8;
            unsigned ao = sb + arow * ASTRB + ak * 2;
            ldsm_x4(qh, ao);
            ldsm_x4(ql, ao + AQ_LO);
#pragma unroll
            for (int j = 0; j < 4; j++) {
                unsigned kh4[4], kl4[4];
                unsigned krow = j * 16 + (mi >> 1) * 8 + r8;
                unsigned kk = s * 16 + (mi & 1) * 8;
                unsigned ko = kb + krow * ASTRB + kk * 2;
                ldsm_x4(kh4, ko);
                ldsm_x4(kl4, ko + KLOF);
                mma_bf16(sacc[2 * j], qh, kh4);
                mma_bf16(sacc[2 * j + 1], qh, kh4 + 2);
                mma_bf16(sacc[2 * j], qh, kl4);
                mma_bf16(sacc[2 * j + 1], qh, kl4 + 2);
                mma_bf16(sacc[2 * j], ql, kh4);
                mma_bf16(sacc[2 * j + 1], ql, kh4 + 2);
            }
        }

        if (kt >= mask_start) {
            int colb = kt * 64 + 2 * (lane & 3);
#pragma unroll
            for (int nt = 0; nt < 8; nt++) {
                int c0 = colb + 8 * nt;
                if (c0 > qpos0)     sacc[nt][0] = -1e30f;
                if (c0 + 1 > qpos0) sacc[nt][1] = -1e30f;
                if (c0 > qpos0 + 8)     sacc[nt][2] = -1e30f;
                if (c0 + 1 > qpos0 + 8) sacc[nt][3] = -1e30f;
            }
        }

        float mx0 = -1e30f, mx1 = -1e30f;
#pragma unroll
        for (int nt = 0; nt < 8; nt++) {
            mx0 = fmaxf(mx0, fmaxf(sacc[nt][0], sacc[nt][1]));
            mx1 = fmaxf(mx1, fmaxf(sacc[nt][2], sacc[nt][3]));
        }
        mx0 = fmaxf(mx0, __shfl_xor_sync(0xffffffffu, mx0, 1));
        mx0 = fmaxf(mx0, __shfl_xor_sync(0xffffffffu, mx0, 2));
        mx1 = fmaxf(mx1, __shfl_xor_sync(0xffffffffu, mx1, 1));
        mx1 = fmaxf(mx1, __shfl_xor_sync(0xffffffffu, mx1, 2));
        float mn0 = fmaxf(mrow0, mx0), mn1 = fmaxf(mrow1, mx1);
        float corr0 = __expf(mrow0 - mn0), corr1 = __expf(mrow1 - mn1);
        float ls0 = 0.f, ls1 = 0.f;
#pragma unroll
        for (int nt = 0; nt < 8; nt++) {
            sacc[nt][0] = __expf(sacc[nt][0] - mn0);
            sacc[nt][1] = __expf(sacc[nt][1] - mn0);
            sacc[nt][2] = __expf(sacc[nt][2] - mn1);
            sacc[nt][3] = __expf(sacc[nt][3] - mn1);
            ls0 += sacc[nt][0] + sacc[nt][1];
            ls1 += sacc[nt][2] + sacc[nt][3];
        }
        ls0 += __shfl_xor_sync(0xffffffffu, ls0, 1);
        ls0 += __shfl_xor_sync(0xffffffffu, ls0, 2);
        ls1 += __shfl_xor_sync(0xffffffffu, ls1, 1);
        ls1 += __shfl_xor_sync(0xffffffffu, ls1, 2);
        lrow0 = lrow0 * corr0 + ls0;
        lrow1 = lrow1 * corr1 + ls1;
        mrow0 = mn0;
        mrow1 = mn1;
#pragma unroll
        for (int nt = 0; nt < 16; nt++) {
            O[nt][0] *= corr0; O[nt][1] *= corr0;
            O[nt][2] *= corr1; O[nt][3] *= corr1;
        }

#pragma unroll
        for (int u = 0; u < 4; u++) {
            unsigned pha[4], pla[4];
            split2(sacc[2 * u][0], sacc[2 * u][1], pha[0], pla[0]);
            split2(sacc[2 * u][2], sacc[2 * u][3], pha[1], pla[1]);
            split2(sacc[2 * u + 1][0], sacc[2 * u + 1][1], pha[2], pla[2]);
            split2(sacc[2 * u + 1][2], sacc[2 * u + 1][3], pha[3], pla[3]);
#pragma unroll
            for (int t = 0; t < 8; t++) {
                unsigned vh4[4], vl4[4];
                unsigned vrow = u * 16 + (mi & 1) * 8 + r8;
                unsigned vdh = t * 16 + (mi >> 1) * 8;
                unsigned vo = vb + vrow * ASTRB + vdh * 2;
                ldsm_x4t(vh4, vo);
                ldsm_x4t(vl4, vo + (VLOF - VHOF));
                mma_bf16(O[2 * t], pha, vh4);
                mma_bf16(O[2 * t + 1], pha, vh4 + 2);
                mma_bf16(O[2 * t], pha, vl4);
                mma_bf16(O[2 * t + 1], pha, vl4 + 2);
                mma_bf16(O[2 * t], pla, vh4);
                mma_bf16(O[2 * t + 1], pla, vh4 + 2);
            }
        }
        __syncthreads();
    }
#undef LOADKV

    float inv0 = 1.f / lrow0, inv1 = 1.f / lrow1;
    int b = bh >> 4, h = bh & 15;
    int r0 = qt * 128 + warp * 16 + (lane >> 2);
    int cbase = h * CDH + 2 * (lane & 3);
#pragma unroll
    for (int nt = 0; nt < 16; nt++) {
#pragma unroll
        for (int e = 0; e < 4; e++) {
            int row = (e < 2) ? r0 : r0 + 8;
            float val = O[nt][e] * ((e < 2) ? inv0 : inv1);
            int col = cbase + nt * 8 + (e & 1);
            size_t off = (size_t)(b * CN + row) * CDIM + col;
            unsigned short hh, ll;
            bf16_split(val, hh, ll);
            g_attn_hi[off] = hh;
            g_attn_lo[off] = ll;
        }
    }
}

// ---------------- launch ----------------------------------------------------
extern "C" void kernel_launch(void* const* d_in, const int* in_sizes, int n_in,
                              void* d_out, int out_size) {
    const float* x      = (const float*)d_in[0];
    const float* past_k = (const float*)d_in[1];
    const float* past_v = (const float*)d_in[2];
    const float* w_qkv  = (const float*)d_in[4];
    const float* w_out  = (const float*)d_in[5];
    const float* ln_g   = (const float*)d_in[6];
    const float* ln_b   = (const float*)d_in[7];

    float* out  = (float*)d_out;                       // [2,1024,2048]
    float* kout = out + (size_t)CB * CN * CDIM;        // [2,16,2048,128]
    float* vout = kout + (size_t)CB * CH * CKV * CDH;  // [2,16,2048,128]

    cudaFuncSetAttribute(attn_mma_kernel,
                         cudaFuncAttributeMaxDynamicSharedMemorySize, SMEM_A3);
    cudaFuncSetAttribute(mma_gemm<NQKV, 1>,
                         cudaFuncAttributeMaxDynamicSharedMemorySize, SMEM_G);
    cudaFuncSetAttribute(mma_gemm<CDIM, 0>,
                         cudaFuncAttributeMaxDynamicSharedMemorySize, SMEM_G);

    // QKV GEMM stays at captured launch index 3
    ln_kernel<<<NTOK, 256>>>(x, ln_g, ln_b);
    transpose_split_kernel<0><<<dim3(NQKV / 32, CDIM / 32), dim3(32, 8)>>>(w_qkv);
    transpose_split_kernel<1><<<dim3(CDIM / 32, CDIM / 32), dim3(32, 8)>>>(w_out);

    mma_gemm<NQKV, 1><<<dim3(24, 16), 256, SMEM_G>>>(nullptr, kout, vout);

    rope_table_kernel<<<512, 256>>>();
    rope_k_kernel<<<(CB * CH * CKV * 64) / 256, 256>>>(past_k, kout);
    split_v_kernel<<<(CB * CH * CKV * 32) / 256, 256>>>(past_v, vout);
    rope_q_kernel<<<(CB * CH * CN * 64) / 256, 256>>>();

    attn_mma_kernel<<<256, 256, SMEM_A3>>>(kout, vout);

    mma_gemm<CDIM, 0><<<dim3(8, 16), 256, SMEM_G>>>(out, nullptr, nullptr);
}

// round 11
// speedup vs baseline: 1.0121x; 1.0121x over previous
#include <cuda_runtime.h>
#include <cuda_bf16.h>
#include <math.h>

// Problem constants
#define CB    2
#define CN    1024
#define CPAST 1024
#define CKV   2048
#define CDIM  2048
#define CH    16
#define CDH   128
#define NTOK  2048            // CB*CN
#define NQKV  6144            // 3*HEADS*DH
#define SCALE 0.08838834764831845f   // 128^-0.5

// ---------------- scratch (device globals; no dynamic alloc allowed) -------
__device__ float g_cos[CKV * 64];
__device__ float g_sin[CKV * 64];
__device__ unsigned short g_xn_hi[NTOK * CDIM];
__device__ unsigned short g_xn_lo[NTOK * CDIM];
__device__ unsigned short g_attn_hi[NTOK * CDIM];
__device__ unsigned short g_attn_lo[NTOK * CDIM];
__device__ unsigned short g_wqkvT_hi[NQKV * CDIM];   // [n][k]
__device__ unsigned short g_wqkvT_lo[NQKV * CDIM];
__device__ unsigned short g_woutT_hi[CDIM * CDIM];   // [n][k]
__device__ unsigned short g_woutT_lo[CDIM * CDIM];
// pre-split attention operands
__device__ unsigned short g_q_hi[CB * CH * CN * CDH];
__device__ unsigned short g_q_lo[CB * CH * CN * CDH];
__device__ unsigned short g_k_hi[CB * CH * CKV * CDH];
__device__ unsigned short g_k_lo[CB * CH * CKV * CDH];
__device__ unsigned short g_v_hi[CB * CH * CKV * CDH];
__device__ unsigned short g_v_lo[CB * CH * CKV * CDH];

extern __shared__ char smem[];

// ---------------- small helpers --------------------------------------------
__device__ __forceinline__ unsigned smem_u32(const void* p) {
    unsigned a;
    asm("{ .reg .u64 t; cvta.to.shared.u64 t, %1; cvt.u32.u64 %0, t; }"
        : "=r"(a) : "l"(p));
    return a;
}

__device__ __forceinline__ void bf16_split(float v, unsigned short& h, unsigned short& l) {
    __nv_bfloat16 bh = __float2bfloat16(v);
    float r = v - __bfloat162float(bh);
    __nv_bfloat16 bl = __float2bfloat16(r);
    h = __bfloat16_as_ushort(bh);
    l = __bfloat16_as_ushort(bl);
}

__device__ __forceinline__ void split2(float a, float b, unsigned& h, unsigned& l) {
    __nv_bfloat16 ah = __float2bfloat16(a), bh_ = __float2bfloat16(b);
    float ar = a - __bfloat162float(ah), br = b - __bfloat162float(bh_);
    __nv_bfloat16 al = __float2bfloat16(ar), bl = __float2bfloat16(br);
    h = (unsigned)__bfloat16_as_ushort(ah) | ((unsigned)__bfloat16_as_ushort(bh_) << 16);
    l = (unsigned)__bfloat16_as_ushort(al) | ((unsigned)__bfloat16_as_ushort(bl) << 16);
}

__device__ __forceinline__ void cp16(unsigned dst, const void* src) {
    asm volatile("cp.async.cg.shared.global [%0], [%1], 16;" :: "r"(dst), "l"(src));
}

__device__ __forceinline__ void ldsm_x4(unsigned* r, unsigned addr) {
    asm volatile("ldmatrix.sync.aligned.m8n8.x4.shared.b16 {%0,%1,%2,%3}, [%4];"
                 : "=r"(r[0]), "=r"(r[1]), "=r"(r[2]), "=r"(r[3]) : "r"(addr));
}

__device__ __forceinline__ void ldsm_x4t(unsigned* r, unsigned addr) {
    asm volatile("ldmatrix.sync.aligned.m8n8.x4.trans.shared.b16 {%0,%1,%2,%3}, [%4];"
                 : "=r"(r[0]), "=r"(r[1]), "=r"(r[2]), "=r"(r[3]) : "r"(addr));
}

__device__ __forceinline__ void mma_bf16(float* c, const unsigned* a, const unsigned* b) {
    asm volatile(
        "mma.sync.aligned.m16n8k16.row.col.f32.bf16.bf16.f32 "
        "{%0,%1,%2,%3}, {%4,%5,%6,%7}, {%8,%9}, {%0,%1,%2,%3};"
        : "+f"(c[0]), "+f"(c[1]), "+f"(c[2]), "+f"(c[3])
        : "r"(a[0]), "r"(a[1]), "r"(a[2]), "r"(a[3]), "r"(b[0]), "r"(b[1]));
}

// ---------------- RoPE table (f32 angles; DP range reduce) -----------------
__global__ void rope_table_kernel() {
    int idx = blockIdx.x * blockDim.x + threadIdx.x;
    if (idx >= CKV * 64) return;
    int pos = idx >> 6, i = idx & 63;
    float w = powf(10000.0f, -((float)i) / 64.0f);
    float ang = (float)pos * w;
    double d = (double)ang;
    double q = rint(d * 0.15915494309189535);   // 1/(2*pi)
    float r = (float)(d - q * 6.283185307179586);
    g_cos[idx] = cosf(r);
    g_sin[idx] = sinf(r);
}

// ---------------- LayerNorm -> bf16 hi/lo ----------------------------------
__global__ void ln_kernel(const float* __restrict__ x,
                          const float* __restrict__ gam,
                          const float* __restrict__ bet) {
    int row = blockIdx.x;
    int tid = threadIdx.x;
    const float* xp = x + (size_t)row * CDIM;

    float4 v1 = *(const float4*)(xp + tid * 8);
    float4 v2 = *(const float4*)(xp + tid * 8 + 4);
    float vals[8] = {v1.x, v1.y, v1.z, v1.w, v2.x, v2.y, v2.z, v2.w};
    float s = 0.f, ss = 0.f;
#pragma unroll
    for (int i = 0; i < 8; i++) { s += vals[i]; ss += vals[i] * vals[i]; }
#pragma unroll
    for (int o = 16; o; o >>= 1) {
        s  += __shfl_xor_sync(0xffffffffu, s, o);
        ss += __shfl_xor_sync(0xffffffffu, ss, o);
    }
    __shared__ float sh_s[8], sh_ss[8];
    __shared__ float sh_mu, sh_rstd;
    int wid = tid >> 5, lane = tid & 31;
    if (lane == 0) { sh_s[wid] = s; sh_ss[wid] = ss; }
    __syncthreads();
    if (tid == 0) {
        float S = 0.f, SS = 0.f;
#pragma unroll
        for (int i = 0; i < 8; i++) { S += sh_s[i]; SS += sh_ss[i]; }
        float mu = S / (float)CDIM;
        float var = SS / (float)CDIM - mu * mu;
        sh_mu = mu;
        sh_rstd = rsqrtf(var + 1e-5f);
    }
    __syncthreads();
    float mu = sh_mu, rstd = sh_rstd;
#pragma unroll
    for (int i = 0; i < 8; i++) {
        int c = tid * 8 + i;
        float v = (vals[i] - mu) * rstd * gam[c] + bet[c];
        unsigned short h, l;
        bf16_split(v, h, l);
        size_t o = (size_t)row * CDIM + c;
        g_xn_hi[o] = h;
        g_xn_lo[o] = l;
    }
}

// ---------------- transpose + bf16 split weights ---------------------------
template <int WSEL>
__global__ void transpose_split_kernel(const float* __restrict__ w) {
    constexpr int N = (WSEL == 0) ? NQKV : CDIM;
    unsigned short* hi = (WSEL == 0) ? g_wqkvT_hi : g_woutT_hi;
    unsigned short* lo = (WSEL == 0) ? g_wqkvT_lo : g_woutT_lo;
    __shared__ float t[32][33];
    int n0 = blockIdx.x * 32, k0 = blockIdx.y * 32;
    int tx = threadIdx.x, ty = threadIdx.y;
#pragma unroll
    for (int i = ty; i < 32; i += 8)
        t[i][tx] = w[(size_t)(k0 + i) * N + n0 + tx];
    __syncthreads();
#pragma unroll
    for (int i = ty; i < 32; i += 8) {
        float v = t[tx][i];
        size_t o = (size_t)(n0 + i) * CDIM + k0 + tx;
        unsigned short h, l;
        bf16_split(v, h, l);
        hi[o] = h;
        lo[o] = l;
    }
}

// ---------------- mma.sync 3xBF16 GEMM (128x128 CTA, occ 2) ----------------
// MODE 1: fused epilogue — RoPE+scale+split Q, RoPE+split K, split V.
#define KC        32
#define MATB      (128 * 40 * 2)     // 10240 B per matrix tile
#define BUFB      (4 * MATB)         // 40960 B per stage
#define SMEM_G    (2 * BUFB)         // 81920 B

template <int NTOT, int MODE>
__global__ __launch_bounds__(256, 2)
void mma_gemm(float* __restrict__ C, float* __restrict__ kout,
              float* __restrict__ vout) {
    const unsigned short* Ah_g = (MODE == 1) ? g_xn_hi : g_attn_hi;
    const unsigned short* Al_g = (MODE == 1) ? g_xn_lo : g_attn_lo;
    const unsigned short* Bh_g = (MODE == 1) ? g_wqkvT_hi : g_woutT_hi;
    const unsigned short* Bl_g = (MODE == 1) ? g_wqkvT_lo : g_woutT_lo;

    unsigned sb = smem_u32(smem);
    int tid = threadIdx.x, warp = tid >> 5, lane = tid & 31;
    int bm = blockIdx.y, bn = blockIdx.x;
    int wm = warp & 3, wn = warp >> 2;

    float acc[2][8][4];
#pragma unroll
    for (int i = 0; i < 2; i++)
#pragma unroll
        for (int j = 0; j < 8; j++)
#pragma unroll
            for (int k = 0; k < 4; k++) acc[i][j][k] = 0.f;

    int s0 = tid, s1 = tid + 256;
    int r0s = s0 >> 2, g0 = s0 & 3;
    int r1s = s1 >> 2, g1 = s1 & 3;

#define LOAD_CHUNK(cc, st)                                                     \
    {                                                                          \
        int k0 = (cc) * KC;                                                    \
        unsigned bufa = sb + (st) * BUFB;                                      \
        size_t ga0 = (size_t)(bm * 128 + r0s) * CDIM + k0 + g0 * 8;            \
        size_t ga1 = (size_t)(bm * 128 + r1s) * CDIM + k0 + g1 * 8;            \
        size_t gb0 = (size_t)(bn * 128 + r0s) * CDIM + k0 + g0 * 8;            \
        size_t gb1 = (size_t)(bn * 128 + r1s) * CDIM + k0 + g1 * 8;            \
        unsigned d0 = r0s * 80 + g0 * 16;                                      \
        unsigned d1 = r1s * 80 + g1 * 16;                                      \
        cp16(bufa + d0, Ah_g + ga0);                                           \
        cp16(bufa + d1, Ah_g + ga1);                                           \
        cp16(bufa + MATB + d0, Al_g + ga0);                                    \
        cp16(bufa + MATB + d1, Al_g + ga1);                                    \
        cp16(bufa + 2 * MATB + d0, Bh_g + gb0);                                \
        cp16(bufa + 2 * MATB + d1, Bh_g + gb1);                                \
        cp16(bufa + 3 * MATB + d0, Bl_g + gb0);                                \
        cp16(bufa + 3 * MATB + d1, Bl_g + gb1);                                \
        asm volatile("cp.async.commit_group;");                                \
    }

    int ami = lane >> 3, ar = lane & 7;
    int a_row = (ami & 1) * 8 + ar;
    int a_col = (ami >> 1) * 8;
    int b_row = (ami >> 1) * 8 + ar;
    int b_col = (ami & 1) * 8;

    LOAD_CHUNK(0, 0);

    for (int c = 0; c < CDIM / KC; c++) {
        int st = c & 1;
        if (c + 1 < CDIM / KC) {
            LOAD_CHUNK(c + 1, st ^ 1);
            asm volatile("cp.async.wait_group 1;");
        } else {
            asm volatile("cp.async.wait_group 0;");
        }
        __syncthreads();

        unsigned Ab = sb + st * BUFB;
        unsigned Bb = Ab + 2 * MATB;
#pragma unroll
        for (int ks = 0; ks < 2; ks++) {
            unsigned ah[2][4], al[2][4];
#pragma unroll
            for (int mt = 0; mt < 2; mt++) {
                unsigned off = (unsigned)((wm * 32 + mt * 16 + a_row) * 80
                                          + (ks * 16 + a_col) * 2);
                ldsm_x4(ah[mt], Ab + off);
                ldsm_x4(al[mt], Ab + MATB + off);
            }
#pragma unroll
            for (int nt2 = 0; nt2 < 4; nt2++) {
                unsigned off = (unsigned)((wn * 64 + nt2 * 16 + b_row) * 80
                                          + (ks * 16 + b_col) * 2);
                unsigned bh4[4], bl4[4];
                ldsm_x4(bh4, Bb + off);
                ldsm_x4(bl4, Bb + MATB + off);
                int n0i = 2 * nt2, n1i = 2 * nt2 + 1;
                mma_bf16(acc[0][n0i], ah[0], bh4);
                mma_bf16(acc[1][n0i], ah[1], bh4);
                mma_bf16(acc[0][n1i], ah[0], bh4 + 2);
                mma_bf16(acc[1][n1i], ah[1], bh4 + 2);
                mma_bf16(acc[0][n0i], ah[0], bl4);
                mma_bf16(acc[1][n0i], ah[1], bl4);
                mma_bf16(acc[0][n1i], ah[0], bl4 + 2);
                mma_bf16(acc[1][n1i], ah[1], bl4 + 2);
                mma_bf16(acc[0][n0i], al[0], bh4);
                mma_bf16(acc[1][n0i], al[1], bh4);
                mma_bf16(acc[0][n1i], al[0], bh4 + 2);
                mma_bf16(acc[1][n1i], al[1], bh4 + 2);
            }
        }
        __syncthreads();
    }

    int crow = lane >> 2, ccol = (lane & 3) * 2;
#pragma unroll
    for (int mt = 0; mt < 2; mt++) {
#pragma unroll
        for (int nt = 0; nt < 8; nt++) {
            int gn = bn * 128 + wn * 64 + nt * 8 + ccol;
#pragma unroll
            for (int h2 = 0; h2 < 2; h2++) {
                int gm = bm * 128 + wm * 32 + mt * 16 + crow + h2 * 8;
                float2 v = make_float2(acc[mt][nt][2 * h2], acc[mt][nt][2 * h2 + 1]);
                if (MODE == 0) {
                    *(float2*)(C + (size_t)gm * NTOT + gn) = v;
                } else {
                    int sec = gn >> 11, w = gn & 2047, h = w >> 7, d0 = w & 127;
                    int b = gm >> 10, nidx = gm & 1023, bh2 = b * CH + h;
                    int pos = CPAST + nidx;
                    unsigned hh, ll;
                    if (sec == 0) {
                        float cc = g_cos[pos * 64 + (d0 >> 1)];
                        float ss = g_sin[pos * 64 + (d0 >> 1)];
                        float ox = (v.x * cc - v.y * ss) * SCALE;
                        float oy = (v.y * cc + v.x * ss) * SCALE;
                        split2(ox, oy, hh, ll);
                        size_t o = ((size_t)bh2 * CN + nidx) * CDH + d0;
                        *(unsigned*)(g_q_hi + o) = hh;
                        *(unsigned*)(g_q_lo + o) = ll;
                    } else if (sec == 1) {
                        float cc = g_cos[pos * 64 + (d0 >> 1)];
                        float ss = g_sin[pos * 64 + (d0 >> 1)];
                        float ox = v.x * cc - v.y * ss;
                        float oy = v.y * cc + v.x * ss;
                        size_t o = ((size_t)bh2 * CKV + pos) * CDH + d0;
                        *(float2*)(kout + o) = make_float2(ox, oy);
                        split2(ox, oy, hh, ll);
                        *(unsigned*)(g_k_hi + o) = hh;
                        *(unsigned*)(g_k_lo + o) = ll;
                    } else {
                        size_t o = ((size_t)bh2 * CKV + pos) * CDH + d0;
                        *(float2*)(vout + o) = v;
                        split2(v.x, v.y, hh, ll);
                        *(unsigned*)(g_v_hi + o) = hh;
                        *(unsigned*)(g_v_lo + o) = ll;
                    }
                }
            }
        }
    }
#undef LOAD_CHUNK
}

// ---------------- RoPE K past half (rope + split) --------------------------
__global__ void rope_k_past_kernel(const float* __restrict__ past_k,
                                   float* __restrict__ kout) {
    int idx = blockIdx.x * blockDim.x + threadIdx.x;   // CB*CH*CPAST*64 pairs
    if (idx >= CB * CH * CPAST * 64) return;
    int i = idx & 63;
    int rest = idx >> 6;          // bh*CPAST + p
    int p = rest & (CPAST - 1);
    int bh = rest >> 10;
    float2 xv = *((const float2*)(past_k + ((size_t)rest << 7)) + i);
    float c = g_cos[p * 64 + i], s = g_sin[p * 64 + i];
    float2 o;
    o.x = xv.x * c - xv.y * s;
    o.y = xv.y * c + xv.x * s;
    size_t dsto = ((size_t)bh * CKV + p) << 6;   // float2 index
    *((float2*)kout + dsto + i) = o;
    unsigned h, l;
    split2(o.x, o.y, h, l);
    ((unsigned*)g_k_hi)[dsto + i] = h;
    ((unsigned*)g_k_lo)[dsto + i] = l;
}

// ---------------- V past half (copy + split) -------------------------------
__global__ void split_v_past_kernel(const float* __restrict__ past_v,
                                    float* __restrict__ vout) {
    int idx = blockIdx.x * blockDim.x + threadIdx.x;   // CB*CH*CPAST*32 f4
    if (idx >= CB * CH * CPAST * 32) return;
    int i4 = idx & 31;
    int rest = idx >> 5;          // bh*CPAST + p
    int p = rest & (CPAST - 1);
    int bh = rest >> 10;
    float4 v = *((const float4*)past_v + ((size_t)rest << 5) + i4);
    size_t dsto = ((size_t)bh * CKV + p) << 5;   // float4 index
    *((float4*)vout + dsto + i4) = v;
    unsigned h0, l0, h1, l1;
    split2(v.x, v.y, h0, l0);
    split2(v.z, v.w, h1, l1);
    ((uint2*)g_v_hi)[dsto + i4] = make_uint2(h0, h1);
    ((uint2*)g_v_lo)[dsto + i4] = make_uint2(l0, l1);
}

// ---------------- flash attention (mma.sync, pre-split, cp.async 2-stage) --
#define ASTRB     272
#define AQ_LO     34816
#define ST0       69632
#define STSZ      69632
#define KLOF      17408
#define VHOF      34816
#define VLOF      52224
#define SMEM_A3   208896

__global__ __launch_bounds__(256, 1) void attn_mma_kernel(
    const float* __restrict__ kc_unused, const float* __restrict__ vc_unused) {
    unsigned sb = smem_u32(smem);
    int id = blockIdx.x;
    int qt = 7 - (id & 7), bh = id >> 3;   // longest CTAs first
    int tid = threadIdx.x, warp = tid >> 5, lane = tid & 31;

    size_t qbase = ((size_t)bh * CN + qt * 128) * CDH;
    size_t kvbase = (size_t)bh * CKV * CDH;

#pragma unroll
    for (int it = 0; it < 16; it++) {
        int slot = tid + it * 256;
        int mat = slot >> 11;
        int r = (slot >> 4) & 127;
        int seg = slot & 15;
        const unsigned short* src = (mat ? g_q_lo : g_q_hi) + qbase + r * CDH + seg * 8;
        cp16(sb + mat * AQ_LO + r * ASTRB + seg * 16, src);
    }

#define LOADKV(kt_, s_)                                                         \
    {                                                                           \
        size_t tb = kvbase + (size_t)(kt_) * 64 * CDH;                          \
        _Pragma("unroll")                                                       \
        for (int it = 0; it < 16; it++) {                                      \
            int slot = tid + it * 256;                                          \
            int mat = slot >> 10;                                               \
            int r = (slot >> 4) & 63;                                           \
            int seg = slot & 15;                                                \
            const unsigned short* src =                                         \
                (mat == 0 ? g_k_hi : mat == 1 ? g_k_lo                          \
                 : mat == 2 ? g_v_hi : g_v_lo) + tb + r * CDH + seg * 8;        \
            cp16(sb + ST0 + (s_) * STSZ + mat * KLOF + r * ASTRB + seg * 16,    \
                 src);                                                          \
        }                                                                       \
        asm volatile("cp.async.commit_group;");                                 \
    }

    LOADKV(0, 0);

    float O[16][4];
#pragma unroll
    for (int i = 0; i < 16; i++)
#pragma unroll
        for (int j = 0; j < 4; j++) O[i][j] = 0.f;
    float mrow0 = -1e30f, mrow1 = -1e30f, lrow0 = 0.f, lrow1 = 0.f;

    int qpos0 = CPAST + qt * 128 + warp * 16 + (lane >> 2);
    int nkt = 18 + 2 * qt;
    int mask_start = nkt - 2;
    int mi = lane >> 3, r8 = lane & 7;

    for (int kt = 0; kt < nkt; kt++) {
        int st = kt & 1;
        if (kt + 1 < nkt) {
            LOADKV(kt + 1, st ^ 1);
            asm volatile("cp.async.wait_group 1;");
        } else {
            asm volatile("cp.async.wait_group 0;");
        }
        __syncthreads();

        unsigned kb = sb + ST0 + st * STSZ;
        unsigned vb = kb + VHOF;

        float sacc[8][4];
#pragma unroll
        for (int i = 0; i < 8; i++)
#pragma unroll
            for (int j = 0; j < 4; j++) sacc[i][j] = 0.f;

#pragma unroll
        for (int s = 0; s < 8; s++) {
            unsigned qh[4], ql[4];
            unsigned arow = warp * 16 + (mi & 1) * 8 + r8;
            unsigned ak = s * 16 + (mi >> 1) * 8;
            unsigned ao = sb + arow * ASTRB + ak * 2;
            ldsm_x4(qh, ao);
            ldsm_x4(ql, ao + AQ_LO);
#pragma unroll
            for (int j = 0; j < 4; j++) {
                unsigned kh4[4], kl4[4];
                unsigned krow = j * 16 + (mi >> 1) * 8 + r8;
                unsigned kk = s * 16 + (mi & 1) * 8;
                unsigned ko = kb + krow * ASTRB + kk * 2;
                ldsm_x4(kh4, ko);
                ldsm_x4(kl4, ko + KLOF);
                mma_bf16(sacc[2 * j], qh, kh4);
                mma_bf16(sacc[2 * j + 1], qh, kh4 + 2);
                mma_bf16(sacc[2 * j], qh, kl4);
                mma_bf16(sacc[2 * j + 1], qh, kl4 + 2);
                mma_bf16(sacc[2 * j], ql, kh4);
                mma_bf16(sacc[2 * j + 1], ql, kh4 + 2);
            }
        }

        if (kt >= mask_start) {
            int colb = kt * 64 + 2 * (lane & 3);
#pragma unroll
            for (int nt = 0; nt < 8; nt++) {
                int c0 = colb + 8 * nt;
                if (c0 > qpos0)     sacc[nt][0] = -1e30f;
                if (c0 + 1 > qpos0) sacc[nt][1] = -1e30f;
                if (c0 > qpos0 + 8)     sacc[nt][2] = -1e30f;
                if (c0 + 1 > qpos0 + 8) sacc[nt][3] = -1e30f;
            }
        }

        float mx0 = -1e30f, mx1 = -1e30f;
#pragma unroll
        for (int nt = 0; nt < 8; nt++) {
            mx0 = fmaxf(mx0, fmaxf(sacc[nt][0], sacc[nt][1]));
            mx1 = fmaxf(mx1, fmaxf(sacc[nt][2], sacc[nt][3]));
        }
        mx0 = fmaxf(mx0, __shfl_xor_sync(0xffffffffu, mx0, 1));
        mx0 = fmaxf(mx0, __shfl_xor_sync(0xffffffffu, mx0, 2));
        mx1 = fmaxf(mx1, __shfl_xor_sync(0xffffffffu, mx1, 1));
        mx1 = fmaxf(mx1, __shfl_xor_sync(0xffffffffu, mx1, 2));
        float mn0 = fmaxf(mrow0, mx0), mn1 = fmaxf(mrow1, mx1);
        float corr0 = __expf(mrow0 - mn0), corr1 = __expf(mrow1 - mn1);
        float ls0 = 0.f, ls1 = 0.f;
#pragma unroll
        for (int nt = 0; nt < 8; nt++) {
            sacc[nt][0] = __expf(sacc[nt][0] - mn0);
            sacc[nt][1] = __expf(sacc[nt][1] - mn0);
            sacc[nt][2] = __expf(sacc[nt][2] - mn1);
            sacc[nt][3] = __expf(sacc[nt][3] - mn1);
            ls0 += sacc[nt][0] + sacc[nt][1];
            ls1 += sacc[nt][2] + sacc[nt][3];
        }
        ls0 += __shfl_xor_sync(0xffffffffu, ls0, 1);
        ls0 += __shfl_xor_sync(0xffffffffu, ls0, 2);
        ls1 += __shfl_xor_sync(0xffffffffu, ls1, 1);
        ls1 += __shfl_xor_sync(0xffffffffu, ls1, 2);
        lrow0 = lrow0 * corr0 + ls0;
        lrow1 = lrow1 * corr1 + ls1;
        mrow0 = mn0;
        mrow1 = mn1;
#pragma unroll
        for (int nt = 0; nt < 16; nt++) {
            O[nt][0] *= corr0; O[nt][1] *= corr0;
            O[nt][2] *= corr1; O[nt][3] *= corr1;
        }

#pragma unroll
        for (int u = 0; u < 4; u++) {
            unsigned pha[4], pla[4];
            split2(sacc[2 * u][0], sacc[2 * u][1], pha[0], pla[0]);
            split2(sacc[2 * u][2], sacc[2 * u][3], pha[1], pla[1]);
            split2(sacc[2 * u + 1][0], sacc[2 * u + 1][1], pha[2], pla[2]);
            split2(sacc[2 * u + 1][2], sacc[2 * u + 1][3], pha[3], pla[3]);
#pragma unroll
            for (int t = 0; t < 8; t++) {
                unsigned vh4[4], vl4[4];
                unsigned vrow = u * 16 + (mi & 1) * 8 + r8;
                unsigned vdh = t * 16 + (mi >> 1) * 8;
                unsigned vo = vb + vrow * ASTRB + vdh * 2;
                ldsm_x4t(vh4, vo);
                ldsm_x4t(vl4, vo + (VLOF - VHOF));
                mma_bf16(O[2 * t], pha, vh4);
                mma_bf16(O[2 * t + 1], pha, vh4 + 2);
                mma_bf16(O[2 * t], pha, vl4);
                mma_bf16(O[2 * t + 1], pha, vl4 + 2);
                mma_bf16(O[2 * t], pla, vh4);
                mma_bf16(O[2 * t + 1], pla, vh4 + 2);
            }
        }
        __syncthreads();
    }
#undef LOADKV

    float inv0 = 1.f / lrow0, inv1 = 1.f / lrow1;
    int b = bh >> 4, h = bh & 15;
    int r0 = qt * 128 + warp * 16 + (lane >> 2);
    int cbase = h * CDH + 2 * (lane & 3);
#pragma unroll
    for (int nt = 0; nt < 16; nt++) {
#pragma unroll
        for (int e = 0; e < 4; e++) {
            int row = (e < 2) ? r0 : r0 + 8;
            float val = O[nt][e] * ((e < 2) ? inv0 : inv1);
            int col = cbase + nt * 8 + (e & 1);
            size_t off = (size_t)(b * CN + row) * CDIM + col;
            unsigned short hh, ll;
            bf16_split(val, hh, ll);
            g_attn_hi[off] = hh;
            g_attn_lo[off] = ll;
        }
    }
}

// ---------------- launch ----------------------------------------------------
extern "C" void kernel_launch(void* const* d_in, const int* in_sizes, int n_in,
                              void* d_out, int out_size) {
    const float* x      = (const float*)d_in[0];
    const float* past_k = (const float*)d_in[1];
    const float* past_v = (const float*)d_in[2];
    const float* w_qkv  = (const float*)d_in[4];
    const float* w_out  = (const float*)d_in[5];
    const float* ln_g   = (const float*)d_in[6];
    const float* ln_b   = (const float*)d_in[7];

    float* out  = (float*)d_out;                       // [2,1024,2048]
    float* kout = out + (size_t)CB * CN * CDIM;        // [2,16,2048,128]
    float* vout = kout + (size_t)CB * CH * CKV * CDH;  // [2,16,2048,128]

    cudaFuncSetAttribute(attn_mma_kernel,
                         cudaFuncAttributeMaxDynamicSharedMemorySize, SMEM_A3);
    cudaFuncSetAttribute(mma_gemm<NQKV, 1>,
                         cudaFuncAttributeMaxDynamicSharedMemorySize, SMEM_G);
    cudaFuncSetAttribute(mma_gemm<CDIM, 0>,
                         cudaFuncAttributeMaxDynamicSharedMemorySize, SMEM_G);

    // QKV GEMM at captured launch index 3; rope table must precede it (fused epilogue)
    ln_kernel<<<NTOK, 256>>>(x, ln_g, ln_b);
    transpose_split_kernel<0><<<dim3(NQKV / 32, CDIM / 32), dim3(32, 8)>>>(w_qkv);
    rope_table_kernel<<<512, 256>>>();

    mma_gemm<NQKV, 1><<<dim3(48, 16), 256, SMEM_G>>>(nullptr, kout, vout);

    transpose_split_kernel<1><<<dim3(CDIM / 32, CDIM / 32), dim3(32, 8)>>>(w_out);
    rope_k_past_kernel<<<(CB * CH * CPAST * 64) / 256, 256>>>(past_k, kout);
    split_v_past_kernel<<<(CB * CH * CPAST * 32) / 256, 256>>>(past_v, vout);

    attn_mma_kernel<<<256, 256, SMEM_A3>>>(kout, vout);

    mma_gemm<CDIM, 0><<<dim3(16, 16), 256, SMEM_G>>>(out, nullptr, nullptr);
}

// round 13
// speedup vs baseline: 1.4065x; 1.3896x over previous
#include <cuda_runtime.h>
#include <cuda_fp16.h>
#include <math.h>

// Problem constants
#define CB    2
#define CN    1024
#define CPAST 1024
#define CKV   2048
#define CDIM  2048
#define CH    16
#define CDH   128
#define NTOK  2048            // CB*CN
#define NQKV  6144            // 3*HEADS*DH
#define SCALE 0.08838834764831845f   // 128^-0.5

// ---------------- scratch (device globals; no dynamic alloc allowed) -------
__device__ float g_cos[CKV * 64];
__device__ float g_sin[CKV * 64];
__device__ unsigned short g_xn_hi[NTOK * CDIM];
__device__ unsigned short g_xn_lo[NTOK * CDIM];
__device__ unsigned short g_attn_hi[NTOK * CDIM];
__device__ unsigned short g_attn_lo[NTOK * CDIM];
__device__ unsigned short g_wqkvT_hi[NQKV * CDIM];   // [n][k] fp16
__device__ unsigned short g_woutT_hi[CDIM * CDIM];   // [n][k] fp16
// pre-split attention operands (fp16)
__device__ unsigned short g_q_hi[CB * CH * CN * CDH];
__device__ unsigned short g_q_lo[CB * CH * CN * CDH];
__device__ unsigned short g_k_hi[CB * CH * CKV * CDH];
__device__ unsigned short g_v_hi[CB * CH * CKV * CDH];

extern __shared__ char smem[];

// ---------------- small helpers --------------------------------------------
__device__ __forceinline__ unsigned smem_u32(const void* p) {
    unsigned a;
    asm("{ .reg .u64 t; cvta.to.shared.u64 t, %1; cvt.u32.u64 %0, t; }"
        : "=r"(a) : "l"(p));
    return a;
}

// fp16 split: one float -> hi + residual lo
__device__ __forceinline__ void f16_split(float v, unsigned short& h, unsigned short& l) {
    __half hh = __float2half(v);
    float r = v - __half2float(hh);
    __half ll = __float2half(r);
    h = __half_as_ushort(hh);
    l = __half_as_ushort(ll);
}

// split two floats -> packed f16x2 hi and lo words (a in low half)
__device__ __forceinline__ void split2h(float a, float b, unsigned& h, unsigned& l) {
    __half ah = __float2half(a), bh = __float2half(b);
    float ar = a - __half2float(ah), br = b - __half2float(bh);
    __half al = __float2half(ar), bl = __float2half(br);
    h = (unsigned)__half_as_ushort(ah) | ((unsigned)__half_as_ushort(bh) << 16);
    l = (unsigned)__half_as_ushort(al) | ((unsigned)__half_as_ushort(bl) << 16);
}

// pack two floats -> one f16x2 word (no residual)
__device__ __forceinline__ unsigned pack2h(float a, float b) {
    __half ah = __float2half(a), bh = __float2half(b);
    return (unsigned)__half_as_ushort(ah) | ((unsigned)__half_as_ushort(bh) << 16);
}

__device__ __forceinline__ void cp16(unsigned dst, const void* src) {
    asm volatile("cp.async.cg.shared.global [%0], [%1], 16;" :: "r"(dst), "l"(src));
}

__device__ __forceinline__ void ldsm_x4(unsigned* r, unsigned addr) {
    asm volatile("ldmatrix.sync.aligned.m8n8.x4.shared.b16 {%0,%1,%2,%3}, [%4];"
                 : "=r"(r[0]), "=r"(r[1]), "=r"(r[2]), "=r"(r[3]) : "r"(addr));
}

__device__ __forceinline__ void ldsm_x4t(unsigned* r, unsigned addr) {
    asm volatile("ldmatrix.sync.aligned.m8n8.x4.trans.shared.b16 {%0,%1,%2,%3}, [%4];"
                 : "=r"(r[0]), "=r"(r[1]), "=r"(r[2]), "=r"(r[3]) : "r"(addr));
}

__device__ __forceinline__ void mma_f16(float* c, const unsigned* a, const unsigned* b) {
    asm volatile(
        "mma.sync.aligned.m16n8k16.row.col.f32.f16.f16.f32 "
        "{%0,%1,%2,%3}, {%4,%5,%6,%7}, {%8,%9}, {%0,%1,%2,%3};"
        : "+f"(c[0]), "+f"(c[1]), "+f"(c[2]), "+f"(c[3])
        : "r"(a[0]), "r"(a[1]), "r"(a[2]), "r"(a[3]), "r"(b[0]), "r"(b[1]));
}

// ---------------- RoPE table (f32 angles; DP range reduce) -----------------
__global__ void rope_table_kernel() {
    int idx = blockIdx.x * blockDim.x + threadIdx.x;
    if (idx >= CKV * 64) return;
    int pos = idx >> 6, i = idx & 63;
    float w = powf(10000.0f, -((float)i) / 64.0f);
    float ang = (float)pos * w;
    double d = (double)ang;
    double q = rint(d * 0.15915494309189535);   // 1/(2*pi)
    float r = (float)(d - q * 6.283185307179586);
    g_cos[idx] = cosf(r);
    g_sin[idx] = sinf(r);
}

// ---------------- LayerNorm -> fp16 hi/lo ----------------------------------
__global__ void ln_kernel(const float* __restrict__ x,
                          const float* __restrict__ gam,
                          const float* __restrict__ bet) {
    int row = blockIdx.x;
    int tid = threadIdx.x;
    const float* xp = x + (size_t)row * CDIM;

    float4 v1 = *(const float4*)(xp + tid * 8);
    float4 v2 = *(const float4*)(xp + tid * 8 + 4);
    float vals[8] = {v1.x, v1.y, v1.z, v1.w, v2.x, v2.y, v2.z, v2.w};
    float s = 0.f, ss = 0.f;
#pragma unroll
    for (int i = 0; i < 8; i++) { s += vals[i]; ss += vals[i] * vals[i]; }
#pragma unroll
    for (int o = 16; o; o >>= 1) {
        s  += __shfl_xor_sync(0xffffffffu, s, o);
        ss += __shfl_xor_sync(0xffffffffu, ss, o);
    }
    __shared__ float sh_s[8], sh_ss[8];
    __shared__ float sh_mu, sh_rstd;
    int wid = tid >> 5, lane = tid & 31;
    if (lane == 0) { sh_s[wid] = s; sh_ss[wid] = ss; }
    __syncthreads();
    if (tid == 0) {
        float S = 0.f, SS = 0.f;
#pragma unroll
        for (int i = 0; i < 8; i++) { S += sh_s[i]; SS += sh_ss[i]; }
        float mu = S / (float)CDIM;
        float var = SS / (float)CDIM - mu * mu;
        sh_mu = mu;
        sh_rstd = rsqrtf(var + 1e-5f);
    }
    __syncthreads();
    float mu = sh_mu, rstd = sh_rstd;
#pragma unroll
    for (int i = 0; i < 8; i++) {
        int c = tid * 8 + i;
        float v = (vals[i] - mu) * rstd * gam[c] + bet[c];
        unsigned short h, l;
        f16_split(v, h, l);
        size_t o = (size_t)row * CDIM + c;
        g_xn_hi[o] = h;
        g_xn_lo[o] = l;
    }
}

// ---------------- transpose weights -> fp16 hi only ------------------------
template <int WSEL>
__global__ void transpose_split_kernel(const float* __restrict__ w) {
    constexpr int N = (WSEL == 0) ? NQKV : CDIM;
    unsigned short* hi = (WSEL == 0) ? g_wqkvT_hi : g_woutT_hi;
    __shared__ float t[32][33];
    int n0 = blockIdx.x * 32, k0 = blockIdx.y * 32;
    int tx = threadIdx.x, ty = threadIdx.y;
#pragma unroll
    for (int i = ty; i < 32; i += 8)
        t[i][tx] = w[(size_t)(k0 + i) * N + n0 + tx];
    __syncthreads();
#pragma unroll
    for (int i = ty; i < 32; i += 8) {
        float v = t[tx][i];
        size_t o = (size_t)(n0 + i) * CDIM + k0 + tx;
        hi[o] = __half_as_ushort(__float2half(v));
    }
}

// ---------------- mma.sync 2xFP16 GEMM (128x128 CTA, occ 2) ----------------
// D = Ah*Bh + Al*Bh ; MODE 1 fused epilogue: RoPE+scale+split Q, RoPE K, V.
#define KC        32
#define MATB      (128 * 40 * 2)     // 10240 B per matrix tile
#define BUFB      (3 * MATB)         // 30720 B per stage (Ah, Al, Bh)
#define SMEM_G    (2 * BUFB)         // 61440 B

template <int NTOT, int MODE>
__global__ __launch_bounds__(256, 2)
void mma_gemm(float* __restrict__ C, float* __restrict__ kout,
              float* __restrict__ vout) {
    const unsigned short* Ah_g = (MODE == 1) ? g_xn_hi : g_attn_hi;
    const unsigned short* Al_g = (MODE == 1) ? g_xn_lo : g_attn_lo;
    const unsigned short* Bh_g = (MODE == 1) ? g_wqkvT_hi : g_woutT_hi;

    unsigned sb = smem_u32(smem);
    int tid = threadIdx.x, warp = tid >> 5, lane = tid & 31;
    int bm = blockIdx.y, bn = blockIdx.x;
    int wm = warp & 3, wn = warp >> 2;

    float acc[2][8][4];
#pragma unroll
    for (int i = 0; i < 2; i++)
#pragma unroll
        for (int j = 0; j < 8; j++)
#pragma unroll
            for (int k = 0; k < 4; k++) acc[i][j][k] = 0.f;

    int s0 = tid, s1 = tid + 256;
    int r0s = s0 >> 2, g0 = s0 & 3;
    int r1s = s1 >> 2, g1 = s1 & 3;

#define LOAD_CHUNK(cc, st)                                                     \
    {                                                                          \
        int k0 = (cc) * KC;                                                    \
        unsigned bufa = sb + (st) * BUFB;                                      \
        size_t ga0 = (size_t)(bm * 128 + r0s) * CDIM + k0 + g0 * 8;            \
        size_t ga1 = (size_t)(bm * 128 + r1s) * CDIM + k0 + g1 * 8;            \
        size_t gb0 = (size_t)(bn * 128 + r0s) * CDIM + k0 + g0 * 8;            \
        size_t gb1 = (size_t)(bn * 128 + r1s) * CDIM + k0 + g1 * 8;            \
        unsigned d0 = r0s * 80 + g0 * 16;                                      \
        unsigned d1 = r1s * 80 + g1 * 16;                                      \
        cp16(bufa + d0, Ah_g + ga0);                                           \
        cp16(bufa + d1, Ah_g + ga1);                                           \
        cp16(bufa + MATB + d0, Al_g + ga0);                                    \
        cp16(bufa + MATB + d1, Al_g + ga1);                                    \
        cp16(bufa + 2 * MATB + d0, Bh_g + gb0);                                \
        cp16(bufa + 2 * MATB + d1, Bh_g + gb1);                                \
        asm volatile("cp.async.commit_group;");                                \
    }

    int ami = lane >> 3, ar = lane & 7;
    int a_row = (ami & 1) * 8 + ar;
    int a_col = (ami >> 1) * 8;
    int b_row = (ami >> 1) * 8 + ar;
    int b_col = (ami & 1) * 8;

    LOAD_CHUNK(0, 0);

    for (int c = 0; c < CDIM / KC; c++) {
        int st = c & 1;
        if (c + 1 < CDIM / KC) {
            LOAD_CHUNK(c + 1, st ^ 1);
            asm volatile("cp.async.wait_group 1;");
        } else {
            asm volatile("cp.async.wait_group 0;");
        }
        __syncthreads();

        unsigned Ab = sb + st * BUFB;
        unsigned Bb = Ab + 2 * MATB;
#pragma unroll
        for (int ks = 0; ks < 2; ks++) {
            unsigned ah[2][4], al[2][4];
#pragma unroll
            for (int mt = 0; mt < 2; mt++) {
                unsigned off = (unsigned)((wm * 32 + mt * 16 + a_row) * 80
                                          + (ks * 16 + a_col) * 2);
                ldsm_x4(ah[mt], Ab + off);
                ldsm_x4(al[mt], Ab + MATB + off);
            }
#pragma unroll
            for (int nt2 = 0; nt2 < 4; nt2++) {
                unsigned off = (unsigned)((wn * 64 + nt2 * 16 + b_row) * 80
                                          + (ks * 16 + b_col) * 2);
                unsigned bh4[4];
                ldsm_x4(bh4, Bb + off);
                int n0i = 2 * nt2, n1i = 2 * nt2 + 1;
                mma_f16(acc[0][n0i], ah[0], bh4);
                mma_f16(acc[1][n0i], ah[1], bh4);
                mma_f16(acc[0][n1i], ah[0], bh4 + 2);
                mma_f16(acc[1][n1i], ah[1], bh4 + 2);
                mma_f16(acc[0][n0i], al[0], bh4);
                mma_f16(acc[1][n0i], al[1], bh4);
                mma_f16(acc[0][n1i], al[0], bh4 + 2);
                mma_f16(acc[1][n1i], al[1], bh4 + 2);
            }
        }
        __syncthreads();
    }

    int crow = lane >> 2, ccol = (lane & 3) * 2;
#pragma unroll
    for (int mt = 0; mt < 2; mt++) {
#pragma unroll
        for (int nt = 0; nt < 8; nt++) {
            int gn = bn * 128 + wn * 64 + nt * 8 + ccol;
#pragma unroll
            for (int h2 = 0; h2 < 2; h2++) {
                int gm = bm * 128 + wm * 32 + mt * 16 + crow + h2 * 8;
                float2 v = make_float2(acc[mt][nt][2 * h2], acc[mt][nt][2 * h2 + 1]);
                if (MODE == 0) {
                    *(float2*)(C + (size_t)gm * NTOT + gn) = v;
                } else {
                    int sec = gn >> 11, w = gn & 2047, h = w >> 7, d0 = w & 127;
                    int b = gm >> 10, nidx = gm & 1023, bh2 = b * CH + h;
                    int pos = CPAST + nidx;
                    if (sec == 0) {
                        float cc = g_cos[pos * 64 + (d0 >> 1)];
                        float ss = g_sin[pos * 64 + (d0 >> 1)];
                        float ox = (v.x * cc - v.y * ss) * SCALE;
                        float oy = (v.y * cc + v.x * ss) * SCALE;
                        unsigned hh, ll;
                        split2h(ox, oy, hh, ll);
                        size_t o = ((size_t)bh2 * CN + nidx) * CDH + d0;
                        *(unsigned*)(g_q_hi + o) = hh;
                        *(unsigned*)(g_q_lo + o) = ll;
                    } else if (sec == 1) {
                        float cc = g_cos[pos * 64 + (d0 >> 1)];
                        float ss = g_sin[pos * 64 + (d0 >> 1)];
                        float ox = v.x * cc - v.y * ss;
                        float oy = v.y * cc + v.x * ss;
                        size_t o = ((size_t)bh2 * CKV + pos) * CDH + d0;
                        *(float2*)(kout + o) = make_float2(ox, oy);
                        *(unsigned*)(g_k_hi + o) = pack2h(ox, oy);
                    } else {
                        size_t o = ((size_t)bh2 * CKV + pos) * CDH + d0;
                        *(float2*)(vout + o) = v;
                        *(unsigned*)(g_v_hi + o) = pack2h(v.x, v.y);
                    }
                }
            }
        }
    }
#undef LOAD_CHUNK
}

// ---------------- RoPE K past half (rope + fp16) ---------------------------
__global__ void rope_k_past_kernel(const float* __restrict__ past_k,
                                   float* __restrict__ kout) {
    int idx = blockIdx.x * blockDim.x + threadIdx.x;   // CB*CH*CPAST*64 pairs
    if (idx >= CB * CH * CPAST * 64) return;
    int i = idx & 63;
    int rest = idx >> 6;          // bh*CPAST + p
    int p = rest & (CPAST - 1);
    int bh = rest >> 10;
    float2 xv = *((const float2*)(past_k + ((size_t)rest << 7)) + i);
    float c = g_cos[p * 64 + i], s = g_sin[p * 64 + i];
    float2 o;
    o.x = xv.x * c - xv.y * s;
    o.y = xv.y * c + xv.x * s;
    size_t dsto = ((size_t)bh * CKV + p) << 6;   // float2 index
    *((float2*)kout + dsto + i) = o;
    ((unsigned*)g_k_hi)[dsto + i] = pack2h(o.x, o.y);
}

// ---------------- V past half (copy + fp16) --------------------------------
__global__ void split_v_past_kernel(const float* __restrict__ past_v,
                                    float* __restrict__ vout) {
    int idx = blockIdx.x * blockDim.x + threadIdx.x;   // CB*CH*CPAST*32 f4
    if (idx >= CB * CH * CPAST * 32) return;
    int i4 = idx & 31;
    int rest = idx >> 5;          // bh*CPAST + p
    int p = rest & (CPAST - 1);
    int bh = rest >> 10;
    float4 v = *((const float4*)past_v + ((size_t)rest << 5) + i4);
    size_t dsto = ((size_t)bh * CKV + p) << 5;   // float4 index
    *((float4*)vout + dsto + i4) = v;
    ((uint2*)g_v_hi)[dsto + i4] = make_uint2(pack2h(v.x, v.y), pack2h(v.z, v.w));
}

// ---------------- flash attention (fp16 2-term, cp.async 2-stage) ----------
#define ASTRB     272
#define AQ_LO     34816
#define ST0       69632
#define STSZ      34816              // KH + VH per stage
#define VHOF      17408
#define SMEM_A3   139264

__global__ __launch_bounds__(256, 1) void attn_mma_kernel(
    const float* __restrict__ kc_unused, const float* __restrict__ vc_unused) {
    unsigned sb = smem_u32(smem);
    int id = blockIdx.x;
    int qt = 7 - (id & 7), bh = id >> 3;   // longest CTAs first
    int tid = threadIdx.x, warp = tid >> 5, lane = tid & 31;

    size_t qbase = ((size_t)bh * CN + qt * 128) * CDH;
    size_t kvbase = (size_t)bh * CKV * CDH;

#pragma unroll
    for (int it = 0; it < 16; it++) {
        int slot = tid + it * 256;
        int mat = slot >> 11;
        int r = (slot >> 4) & 127;
        int seg = slot & 15;
        const unsigned short* src = (mat ? g_q_lo : g_q_hi) + qbase + r * CDH + seg * 8;
        cp16(sb + mat * AQ_LO + r * ASTRB + seg * 16, src);
    }

#define LOADKV(kt_, s_)                                                         \
    {                                                                           \
        size_t tb = kvbase + (size_t)(kt_) * 64 * CDH;                          \
        _Pragma("unroll")                                                       \
        for (int it = 0; it < 8; it++) {                                        \
            int slot = tid + it * 256;                                          \
            int mat = slot >> 10;                                               \
            int r = (slot >> 4) & 63;                                           \
            int seg = slot & 15;                                                \
            const unsigned short* src =                                         \
                (mat ? g_v_hi : g_k_hi) + tb + r * CDH + seg * 8;               \
            cp16(sb + ST0 + (s_) * STSZ + mat * VHOF + r * ASTRB + seg * 16,    \
                 src);                                                          \
        }                                                                       \
        asm volatile("cp.async.commit_group;");                                 \
    }

    LOADKV(0, 0);

    float O[16][4];
#pragma unroll
    for (int i = 0; i < 16; i++)
#pragma unroll
        for (int j = 0; j < 4; j++) O[i][j] = 0.f;
    float mrow0 = -1e30f, mrow1 = -1e30f, lrow0 = 0.f, lrow1 = 0.f;

    int qpos0 = CPAST + qt * 128 + warp * 16 + (lane >> 2);
    int nkt = 18 + 2 * qt;
    int mask_start = nkt - 2;
    int mi = lane >> 3, r8 = lane & 7;

    for (int kt = 0; kt < nkt; kt++) {
        int st = kt & 1;
        if (kt + 1 < nkt) {
            LOADKV(kt + 1, st ^ 1);
            asm volatile("cp.async.wait_group 1;");
        } else {
            asm volatile("cp.async.wait_group 0;");
        }
        __syncthreads();

        unsigned kb = sb + ST0 + st * STSZ;
        unsigned vb = kb + VHOF;

        float sacc[8][4];
#pragma unroll
        for (int i = 0; i < 8; i++)
#pragma unroll
            for (int j = 0; j < 4; j++) sacc[i][j] = 0.f;

#pragma unroll
        for (int s = 0; s < 8; s++) {
            unsigned qh[4], ql[4];
            unsigned arow = warp * 16 + (mi & 1) * 8 + r8;
            unsigned ak = s * 16 + (mi >> 1) * 8;
            unsigned ao = sb + arow * ASTRB + ak * 2;
            ldsm_x4(qh, ao);
            ldsm_x4(ql, ao + AQ_LO);
#pragma unroll
            for (int j = 0; j < 4; j++) {
                unsigned kh4[4];
                unsigned krow = j * 16 + (mi >> 1) * 8 + r8;
                unsigned kk = s * 16 + (mi & 1) * 8;
                unsigned ko = kb + krow * ASTRB + kk * 2;
                ldsm_x4(kh4, ko);
                mma_f16(sacc[2 * j], qh, kh4);
                mma_f16(sacc[2 * j + 1], qh, kh4 + 2);
                mma_f16(sacc[2 * j], ql, kh4);
                mma_f16(sacc[2 * j + 1], ql, kh4 + 2);
            }
        }

        if (kt >= mask_start) {
            int colb = kt * 64 + 2 * (lane & 3);
#pragma unroll
            for (int nt = 0; nt < 8; nt++) {
                int c0 = colb + 8 * nt;
                if (c0 > qpos0)     sacc[nt][0] = -1e30f;
                if (c0 + 1 > qpos0) sacc[nt][1] = -1e30f;
                if (c0 > qpos0 + 8)     sacc[nt][2] = -1e30f;
                if (c0 + 1 > qpos0 + 8) sacc[nt][3] = -1e30f;
            }
        }

        float mx0 = -1e30f, mx1 = -1e30f;
#pragma unroll
        for (int nt = 0; nt < 8; nt++) {
            mx0 = fmaxf(mx0, fmaxf(sacc[nt][0], sacc[nt][1]));
            mx1 = fmaxf(mx1, fmaxf(sacc[nt][2], sacc[nt][3]));
        }
        mx0 = fmaxf(mx0, __shfl_xor_sync(0xffffffffu, mx0, 1));
        mx0 = fmaxf(mx0, __shfl_xor_sync(0xffffffffu, mx0, 2));
        mx1 = fmaxf(mx1, __shfl_xor_sync(0xffffffffu, mx1, 1));
        mx1 = fmaxf(mx1, __shfl_xor_sync(0xffffffffu, mx1, 2));
        float mn0 = fmaxf(mrow0, mx0), mn1 = fmaxf(mrow1, mx1);
        float corr0 = __expf(mrow0 - mn0), corr1 = __expf(mrow1 - mn1);
        float ls0 = 0.f, ls1 = 0.f;
#pragma unroll
        for (int nt = 0; nt < 8; nt++) {
            sacc[nt][0] = __expf(sacc[nt][0] - mn0);
            sacc[nt][1] = __expf(sacc[nt][1] - mn0);
            sacc[nt][2] = __expf(sacc[nt][2] - mn1);
            sacc[nt][3] = __expf(sacc[nt][3] - mn1);
            ls0 += sacc[nt][0] + sacc[nt][1];
            ls1 += sacc[nt][2] + sacc[nt][3];
        }
        ls0 += __shfl_xor_sync(0xffffffffu, ls0, 1);
        ls0 += __shfl_xor_sync(0xffffffffu, ls0, 2);
        ls1 += __shfl_xor_sync(0xffffffffu, ls1, 1);
        ls1 += __shfl_xor_sync(0xffffffffu, ls1, 2);
        lrow0 = lrow0 * corr0 + ls0;
        lrow1 = lrow1 * corr1 + ls1;
        mrow0 = mn0;
        mrow1 = mn1;
#pragma unroll
        for (int nt = 0; nt < 16; nt++) {
            O[nt][0] *= corr0; O[nt][1] *= corr0;
            O[nt][2] *= corr1; O[nt][3] *= corr1;
        }

#pragma unroll
        for (int u = 0; u < 4; u++) {
            unsigned pha[4], pla[4];
            split2h(sacc[2 * u][0], sacc[2 * u][1], pha[0], pla[0]);
            split2h(sacc[2 * u][2], sacc[2 * u][3], pha[1], pla[1]);
            split2h(sacc[2 * u + 1][0], sacc[2 * u + 1][1], pha[2], pla[2]);
            split2h(sacc[2 * u + 1][2], sacc[2 * u + 1][3], pha[3], pla[3]);
#pragma unroll
            for (int t = 0; t < 8; t++) {
                unsigned vh4[4];
                unsigned vrow = u * 16 + (mi & 1) * 8 + r8;
                unsigned vdh = t * 16 + (mi >> 1) * 8;
                unsigned vo = vb + vrow * ASTRB + vdh * 2;
                ldsm_x4t(vh4, vo);
                mma_f16(O[2 * t], pha, vh4);
                mma_f16(O[2 * t + 1], pha, vh4 + 2);
                mma_f16(O[2 * t], pla, vh4);
                mma_f16(O[2 * t + 1], pla, vh4 + 2);
            }
        }
        __syncthreads();
    }
#undef LOADKV

    float inv0 = 1.f / lrow0, inv1 = 1.f / lrow1;
    int b = bh >> 4, h = bh & 15;
    int r0 = qt * 128 + warp * 16 + (lane >> 2);
    int cbase = h * CDH + 2 * (lane & 3);
#pragma unroll
    for (int nt = 0; nt < 16; nt++) {
#pragma unroll
        for (int e = 0; e < 4; e++) {
            int row = (e < 2) ? r0 : r0 + 8;
            float val = O[nt][e] * ((e < 2) ? inv0 : inv1);
            int col = cbase + nt * 8 + (e & 1);
            size_t off = (size_t)(b * CN + row) * CDIM + col;
            unsigned short hh, ll;
            f16_split(val, hh, ll);
            g_attn_hi[off] = hh;
            g_attn_lo[off] = ll;
        }
    }
}

// ---------------- launch ----------------------------------------------------
extern "C" void kernel_launch(void* const* d_in, const int* in_sizes, int n_in,
                              void* d_out, int out_size) {
    const float* x      = (const float*)d_in[0];
    const float* past_k = (const float*)d_in[1];
    const float* past_v = (const float*)d_in[2];
    const float* w_qkv  = (const float*)d_in[4];
    const float* w_out  = (const float*)d_in[5];
    const float* ln_g   = (const float*)d_in[6];
    const float* ln_b   = (const float*)d_in[7];

    float* out  = (float*)d_out;                       // [2,1024,2048]
    float* kout = out + (size_t)CB * CN * CDIM;        // [2,16,2048,128]
    float* vout = kout + (size_t)CB * CH * CKV * CDH;  // [2,16,2048,128]

    cudaFuncSetAttribute(attn_mma_kernel,
                         cudaFuncAttributeMaxDynamicSharedMemorySize, SMEM_A3);
    cudaFuncSetAttribute(mma_gemm<NQKV, 1>,
                         cudaFuncAttributeMaxDynamicSharedMemorySize, SMEM_G);
    cudaFuncSetAttribute(mma_gemm<CDIM, 0>,
                         cudaFuncAttributeMaxDynamicSharedMemorySize, SMEM_G);

    // QKV GEMM at captured launch index 3; rope table precedes it (fused epilogue)
    ln_kernel<<<NTOK, 256>>>(x, ln_g, ln_b);
    transpose_split_kernel<0><<<dim3(NQKV / 32, CDIM / 32), dim3(32, 8)>>>(w_qkv);
    rope_table_kernel<<<512, 256>>>();

    mma_gemm<NQKV, 1><<<dim3(48, 16), 256, SMEM_G>>>(nullptr, kout, vout);

    transpose_split_kernel<1><<<dim3(CDIM / 32, CDIM / 32), dim3(32, 8)>>>(w_out);
    rope_k_past_kernel<<<(CB * CH * CPAST * 64) / 256, 256>>>(past_k, kout);
    split_v_past_kernel<<<(CB * CH * CPAST * 32) / 256, 256>>>(past_v, vout);

    attn_mma_kernel<<<256, 256, SMEM_A3>>>(kout, vout);

    mma_gemm<CDIM, 0><<<dim3(16, 16), 256, SMEM_G>>>(out, nullptr, nullptr);
}

// round 16
// speedup vs baseline: 1.5408x; 1.0955x over previous
#include <cuda_runtime.h>
#include <cuda_fp16.h>
#include <math.h>

// Problem constants
#define CB    2
#define CN    1024
#define CPAST 1024
#define CKV   2048
#define CDIM  2048
#define CH    16
#define CDH   128
#define NTOK  2048            // CB*CN
#define NQKV  6144            // 3*HEADS*DH
#define SCALE 0.08838834764831845f   // 128^-0.5

// ---------------- scratch (device globals; no dynamic alloc allowed) -------
__device__ float g_cos[CKV * 64];
__device__ float g_sin[CKV * 64];
__device__ unsigned short g_xn_hi[NTOK * CDIM];
__device__ unsigned short g_xn_lo[NTOK * CDIM];
__device__ unsigned short g_attn_hi[NTOK * CDIM];
__device__ unsigned short g_attn_lo[NTOK * CDIM];
__device__ unsigned short g_wqkvT_hi[NQKV * CDIM];   // [n][k] fp16
__device__ unsigned short g_woutT_hi[CDIM * CDIM];   // [n][k] fp16
// pre-split attention operands (fp16)
__device__ unsigned short g_q_hi[CB * CH * CN * CDH];
__device__ unsigned short g_q_lo[CB * CH * CN * CDH];
__device__ unsigned short g_k_hi[CB * CH * CKV * CDH];
__device__ unsigned short g_v_hi[CB * CH * CKV * CDH];

extern __shared__ char smem[];

// ---------------- small helpers --------------------------------------------
__device__ __forceinline__ unsigned smem_u32(const void* p) {
    unsigned a;
    asm("{ .reg .u64 t; cvta.to.shared.u64 t, %1; cvt.u32.u64 %0, t; }"
        : "=r"(a) : "l"(p));
    return a;
}

// fp16 split: one float -> hi + residual lo
__device__ __forceinline__ void f16_split(float v, unsigned short& h, unsigned short& l) {
    __half hh = __float2half(v);
    float r = v - __half2float(hh);
    __half ll = __float2half(r);
    h = __half_as_ushort(hh);
    l = __half_as_ushort(ll);
}

// split two floats -> packed f16x2 hi and lo words (a in low half)
__device__ __forceinline__ void split2h(float a, float b, unsigned& h, unsigned& l) {
    __half ah = __float2half(a), bh = __float2half(b);
    float ar = a - __half2float(ah), br = b - __half2float(bh);
    __half al = __float2half(ar), bl = __float2half(br);
    h = (unsigned)__half_as_ushort(ah) | ((unsigned)__half_as_ushort(bh) << 16);
    l = (unsigned)__half_as_ushort(al) | ((unsigned)__half_as_ushort(bl) << 16);
}

// pack two floats -> one f16x2 word (no residual)
__device__ __forceinline__ unsigned pack2h(float a, float b) {
    __half ah = __float2half(a), bh = __float2half(b);
    return (unsigned)__half_as_ushort(ah) | ((unsigned)__half_as_ushort(bh) << 16);
}

__device__ __forceinline__ void cp16(unsigned dst, const void* src) {
    asm volatile("cp.async.cg.shared.global [%0], [%1], 16;" :: "r"(dst), "l"(src));
}

__device__ __forceinline__ void ldsm_x4(unsigned* r, unsigned addr) {
    asm volatile("ldmatrix.sync.aligned.m8n8.x4.shared.b16 {%0,%1,%2,%3}, [%4];"
                 : "=r"(r[0]), "=r"(r[1]), "=r"(r[2]), "=r"(r[3]) : "r"(addr));
}

__device__ __forceinline__ void ldsm_x4t(unsigned* r, unsigned addr) {
    asm volatile("ldmatrix.sync.aligned.m8n8.x4.trans.shared.b16 {%0,%1,%2,%3}, [%4];"
                 : "=r"(r[0]), "=r"(r[1]), "=r"(r[2]), "=r"(r[3]) : "r"(addr));
}

__device__ __forceinline__ void mma_f16(float* c, const unsigned* a, const unsigned* b) {
    asm volatile(
        "mma.sync.aligned.m16n8k16.row.col.f32.f16.f16.f32 "
        "{%0,%1,%2,%3}, {%4,%5,%6,%7}, {%8,%9}, {%0,%1,%2,%3};"
        : "+f"(c[0]), "+f"(c[1]), "+f"(c[2]), "+f"(c[3])
        : "r"(a[0]), "r"(a[1]), "r"(a[2]), "r"(a[3]), "r"(b[0]), "r"(b[1]));
}

// ---------------- RoPE table (f32 angles; DP range reduce) -----------------
__global__ void rope_table_kernel() {
    int idx = blockIdx.x * blockDim.x + threadIdx.x;
    if (idx >= CKV * 64) return;
    int pos = idx >> 6, i = idx & 63;
    float w = powf(10000.0f, -((float)i) / 64.0f);
    float ang = (float)pos * w;
    double d = (double)ang;
    double q = rint(d * 0.15915494309189535);   // 1/(2*pi)
    float r = (float)(d - q * 6.283185307179586);
    g_cos[idx] = cosf(r);
    g_sin[idx] = sinf(r);
}

// ---------------- LayerNorm -> fp16 hi/lo ----------------------------------
__global__ void ln_kernel(const float* __restrict__ x,
                          const float* __restrict__ gam,
                          const float* __restrict__ bet) {
    int row = blockIdx.x;
    int tid = threadIdx.x;
    const float* xp = x + (size_t)row * CDIM;

    float4 v1 = *(const float4*)(xp + tid * 8);
    float4 v2 = *(const float4*)(xp + tid * 8 + 4);
    float vals[8] = {v1.x, v1.y, v1.z, v1.w, v2.x, v2.y, v2.z, v2.w};
    float s = 0.f, ss = 0.f;
#pragma unroll
    for (int i = 0; i < 8; i++) { s += vals[i]; ss += vals[i] * vals[i]; }
#pragma unroll
    for (int o = 16; o; o >>= 1) {
        s  += __shfl_xor_sync(0xffffffffu, s, o);
        ss += __shfl_xor_sync(0xffffffffu, ss, o);
    }
    __shared__ float sh_s[8], sh_ss[8];
    __shared__ float sh_mu, sh_rstd;
    int wid = tid >> 5, lane = tid & 31;
    if (lane == 0) { sh_s[wid] = s; sh_ss[wid] = ss; }
    __syncthreads();
    if (tid == 0) {
        float S = 0.f, SS = 0.f;
#pragma unroll
        for (int i = 0; i < 8; i++) { S += sh_s[i]; SS += sh_ss[i]; }
        float mu = S / (float)CDIM;
        float var = SS / (float)CDIM - mu * mu;
        sh_mu = mu;
        sh_rstd = rsqrtf(var + 1e-5f);
    }
    __syncthreads();
    float mu = sh_mu, rstd = sh_rstd;
#pragma unroll
    for (int i = 0; i < 8; i++) {
        int c = tid * 8 + i;
        float v = (vals[i] - mu) * rstd * gam[c] + bet[c];
        unsigned short h, l;
        f16_split(v, h, l);
        size_t o = (size_t)row * CDIM + c;
        g_xn_hi[o] = h;
        g_xn_lo[o] = l;
    }
}

// ---------------- transpose weights -> fp16 hi only ------------------------
template <int WSEL>
__global__ void transpose_split_kernel(const float* __restrict__ w) {
    constexpr int N = (WSEL == 0) ? NQKV : CDIM;
    unsigned short* hi = (WSEL == 0) ? g_wqkvT_hi : g_woutT_hi;
    __shared__ float t[32][33];
    int n0 = blockIdx.x * 32, k0 = blockIdx.y * 32;
    int tx = threadIdx.x, ty = threadIdx.y;
#pragma unroll
    for (int i = ty; i < 32; i += 8)
        t[i][tx] = w[(size_t)(k0 + i) * N + n0 + tx];
    __syncthreads();
#pragma unroll
    for (int i = ty; i < 32; i += 8) {
        float v = t[tx][i];
        size_t o = (size_t)(n0 + i) * CDIM + k0 + tx;
        hi[o] = __half_as_ushort(__float2half(v));
    }
}

// ---------------- mma.sync FP16 GEMM (128x128 CTA, occ 2) ------------------
// Q columns (bn<16 in MODE 1) and MODE 0: D = Ah*Bh + Al*Bh (2-term).
// K/V columns (bn>=16, MODE 1): D = Ah*Bh (single term).
#define KC        32
#define MATB      (128 * 40 * 2)     // 10240 B per matrix tile
#define BUFB      (3 * MATB)         // 30720 B per stage (Ah, Al, Bh)
#define SMEM_G    (2 * BUFB)         // 61440 B

template <int NTOT, int MODE>
__global__ __launch_bounds__(256, 2)
void mma_gemm(float* __restrict__ C, float* __restrict__ kout,
              float* __restrict__ vout) {
    const unsigned short* Ah_g = (MODE == 1) ? g_xn_hi : g_attn_hi;
    const unsigned short* Al_g = (MODE == 1) ? g_xn_lo : g_attn_lo;
    const unsigned short* Bh_g = (MODE == 1) ? g_wqkvT_hi : g_woutT_hi;

    unsigned sb = smem_u32(smem);
    int tid = threadIdx.x, warp = tid >> 5, lane = tid & 31;
    int bm = blockIdx.y, bn = blockIdx.x;
    int wm = warp & 3, wn = warp >> 2;
    const bool use_lo = (MODE == 0) || (bn < 16);   // Q section keeps residual

    float acc[2][8][4];
#pragma unroll
    for (int i = 0; i < 2; i++)
#pragma unroll
        for (int j = 0; j < 8; j++)
#pragma unroll
            for (int k = 0; k < 4; k++) acc[i][j][k] = 0.f;

    int s0 = tid, s1 = tid + 256;
    int r0s = s0 >> 2, g0 = s0 & 3;
    int r1s = s1 >> 2, g1 = s1 & 3;

#define LOAD_CHUNK(cc, st)                                                     \
    {                                                                          \
        int k0 = (cc) * KC;                                                    \
        unsigned bufa = sb + (st) * BUFB;                                      \
        size_t ga0 = (size_t)(bm * 128 + r0s) * CDIM + k0 + g0 * 8;            \
        size_t ga1 = (size_t)(bm * 128 + r1s) * CDIM + k0 + g1 * 8;            \
        size_t gb0 = (size_t)(bn * 128 + r0s) * CDIM + k0 + g0 * 8;            \
        size_t gb1 = (size_t)(bn * 128 + r1s) * CDIM + k0 + g1 * 8;            \
        unsigned d0 = r0s * 80 + g0 * 16;                                      \
        unsigned d1 = r1s * 80 + g1 * 16;                                      \
        cp16(bufa + d0, Ah_g + ga0);                                           \
        cp16(bufa + d1, Ah_g + ga1);                                           \
        if (use_lo) {                                                          \
            cp16(bufa + MATB + d0, Al_g + ga0);                                \
            cp16(bufa + MATB + d1, Al_g + ga1);                                \
        }                                                                      \
        cp16(bufa + 2 * MATB + d0, Bh_g + gb0);                                \
        cp16(bufa + 2 * MATB + d1, Bh_g + gb1);                                \
        asm volatile("cp.async.commit_group;");                                \
    }

    int ami = lane >> 3, ar = lane & 7;
    int a_row = (ami & 1) * 8 + ar;
    int a_col = (ami >> 1) * 8;
    int b_row = (ami >> 1) * 8 + ar;
    int b_col = (ami & 1) * 8;

    LOAD_CHUNK(0, 0);

    for (int c = 0; c < CDIM / KC; c++) {
        int st = c & 1;
        if (c + 1 < CDIM / KC) {
            LOAD_CHUNK(c + 1, st ^ 1);
            asm volatile("cp.async.wait_group 1;");
        } else {
            asm volatile("cp.async.wait_group 0;");
        }
        __syncthreads();

        unsigned Ab = sb + st * BUFB;
        unsigned Bb = Ab + 2 * MATB;
#pragma unroll
        for (int ks = 0; ks < 2; ks++) {
            unsigned ah[2][4], al[2][4];
#pragma unroll
            for (int mt = 0; mt < 2; mt++) {
                unsigned off = (unsigned)((wm * 32 + mt * 16 + a_row) * 80
                                          + (ks * 16 + a_col) * 2);
                ldsm_x4(ah[mt], Ab + off);
                if (use_lo) ldsm_x4(al[mt], Ab + MATB + off);
            }
#pragma unroll
            for (int nt2 = 0; nt2 < 4; nt2++) {
                unsigned off = (unsigned)((wn * 64 + nt2 * 16 + b_row) * 80
                                          + (ks * 16 + b_col) * 2);
                unsigned bh4[4];
                ldsm_x4(bh4, Bb + off);
                int n0i = 2 * nt2, n1i = 2 * nt2 + 1;
                mma_f16(acc[0][n0i], ah[0], bh4);
                mma_f16(acc[1][n0i], ah[1], bh4);
                mma_f16(acc[0][n1i], ah[0], bh4 + 2);
                mma_f16(acc[1][n1i], ah[1], bh4 + 2);
                if (use_lo) {
                    mma_f16(acc[0][n0i], al[0], bh4);
                    mma_f16(acc[1][n0i], al[1], bh4);
                    mma_f16(acc[0][n1i], al[0], bh4 + 2);
                    mma_f16(acc[1][n1i], al[1], bh4 + 2);
                }
            }
        }
        __syncthreads();
    }

    int crow = lane >> 2, ccol = (lane & 3) * 2;
#pragma unroll
    for (int mt = 0; mt < 2; mt++) {
#pragma unroll
        for (int nt = 0; nt < 8; nt++) {
            int gn = bn * 128 + wn * 64 + nt * 8 + ccol;
#pragma unroll
            for (int h2 = 0; h2 < 2; h2++) {
                int gm = bm * 128 + wm * 32 + mt * 16 + crow + h2 * 8;
                float2 v = make_float2(acc[mt][nt][2 * h2], acc[mt][nt][2 * h2 + 1]);
                if (MODE == 0) {
                    *(float2*)(C + (size_t)gm * NTOT + gn) = v;
                } else {
                    int sec = gn >> 11, w = gn & 2047, h = w >> 7, d0 = w & 127;
                    int b = gm >> 10, nidx = gm & 1023, bh2 = b * CH + h;
                    int pos = CPAST + nidx;
                    if (sec == 0) {
                        float cc = g_cos[pos * 64 + (d0 >> 1)];
                        float ss = g_sin[pos * 64 + (d0 >> 1)];
                        float ox = (v.x * cc - v.y * ss) * SCALE;
                        float oy = (v.y * cc + v.x * ss) * SCALE;
                        unsigned hh, ll;
                        split2h(ox, oy, hh, ll);
                        size_t o = ((size_t)bh2 * CN + nidx) * CDH + d0;
                        *(unsigned*)(g_q_hi + o) = hh;
                        *(unsigned*)(g_q_lo + o) = ll;
                    } else if (sec == 1) {
                        float cc = g_cos[pos * 64 + (d0 >> 1)];
                        float ss = g_sin[pos * 64 + (d0 >> 1)];
                        float ox = v.x * cc - v.y * ss;
                        float oy = v.y * cc + v.x * ss;
                        size_t o = ((size_t)bh2 * CKV + pos) * CDH + d0;
                        *(float2*)(kout + o) = make_float2(ox, oy);
                        *(unsigned*)(g_k_hi + o) = pack2h(ox, oy);
                    } else {
                        size_t o = ((size_t)bh2 * CKV + pos) * CDH + d0;
                        *(float2*)(vout + o) = v;
                        *(unsigned*)(g_v_hi + o) = pack2h(v.x, v.y);
                    }
                }
            }
        }
    }
#undef LOAD_CHUNK
}

// ---------------- RoPE K past half (rope + fp16) ---------------------------
__global__ void rope_k_past_kernel(const float* __restrict__ past_k,
                                   float* __restrict__ kout) {
    int idx = blockIdx.x * blockDim.x + threadIdx.x;   // CB*CH*CPAST*64 pairs
    if (idx >= CB * CH * CPAST * 64) return;
    int i = idx & 63;
    int rest = idx >> 6;          // bh*CPAST + p
    int p = rest & (CPAST - 1);
    int bh = rest >> 10;
    float2 xv = *((const float2*)(past_k + ((size_t)rest << 7)) + i);
    float c = g_cos[p * 64 + i], s = g_sin[p * 64 + i];
    float2 o;
    o.x = xv.x * c - xv.y * s;
    o.y = xv.y * c + xv.x * s;
    size_t dsto = ((size_t)bh * CKV + p) << 6;   // float2 index
    *((float2*)kout + dsto + i) = o;
    ((unsigned*)g_k_hi)[dsto + i] = pack2h(o.x, o.y);
}

// ---------------- V past half (copy + fp16) --------------------------------
__global__ void split_v_past_kernel(const float* __restrict__ past_v,
                                    float* __restrict__ vout) {
    int idx = blockIdx.x * blockDim.x + threadIdx.x;   // CB*CH*CPAST*32 f4
    if (idx >= CB * CH * CPAST * 32) return;
    int i4 = idx & 31;
    int rest = idx >> 5;          // bh*CPAST + p
    int p = rest & (CPAST - 1);
    int bh = rest >> 10;
    float4 v = *((const float4*)past_v + ((size_t)rest << 5) + i4);
    size_t dsto = ((size_t)bh * CKV + p) << 5;   // float4 index
    *((float4*)vout + dsto + i4) = v;
    ((uint2*)g_v_hi)[dsto + i4] = make_uint2(pack2h(v.x, v.y), pack2h(v.z, v.w));
}

// ---------------- flash attention (fp16, 2-term S, 1-term PV) --------------
#define ASTRB     272
#define AQ_LO     34816
#define ST0       69632
#define STSZ      34816              // KH + VH per stage
#define VHOF      17408
#define SMEM_A3   139264

__global__ __launch_bounds__(256, 1) void attn_mma_kernel(
    const float* __restrict__ kc_unused, const float* __restrict__ vc_unused) {
    unsigned sb = smem_u32(smem);
    int id = blockIdx.x;
    int qt = 7 - (id & 7), bh = id >> 3;   // longest CTAs first
    int tid = threadIdx.x, warp = tid >> 5, lane = tid & 31;

    size_t qbase = ((size_t)bh * CN + qt * 128) * CDH;
    size_t kvbase = (size_t)bh * CKV * CDH;

#pragma unroll
    for (int it = 0; it < 16; it++) {
        int slot = tid + it * 256;
        int mat = slot >> 11;
        int r = (slot >> 4) & 127;
        int seg = slot & 15;
        const unsigned short* src = (mat ? g_q_lo : g_q_hi) + qbase + r * CDH + seg * 8;
        cp16(sb + mat * AQ_LO + r * ASTRB + seg * 16, src);
    }

#define LOADKV(kt_, s_)                                                         \
    {                                                                           \
        size_t tb = kvbase + (size_t)(kt_) * 64 * CDH;                          \
        _Pragma("unroll")                                                       \
        for (int it = 0; it < 8; it++) {                                        \
            int slot = tid + it * 256;                                          \
            int mat = slot >> 10;                                               \
            int r = (slot >> 4) & 63;                                           \
            int seg = slot & 15;                                                \
            const unsigned short* src =                                         \
                (mat ? g_v_hi : g_k_hi) + tb + r * CDH + seg * 8;               \
            cp16(sb + ST0 + (s_) * STSZ + mat * VHOF + r * ASTRB + seg * 16,    \
                 src);                                                          \
        }                                                                       \
        asm volatile("cp.async.commit_group;");                                 \
    }

    LOADKV(0, 0);

    float O[16][4];
#pragma unroll
    for (int i = 0; i < 16; i++)
#pragma unroll
        for (int j = 0; j < 4; j++) O[i][j] = 0.f;
    float mrow0 = -1e30f, mrow1 = -1e30f, lrow0 = 0.f, lrow1 = 0.f;

    int qpos0 = CPAST + qt * 128 + warp * 16 + (lane >> 2);
    int nkt = 18 + 2 * qt;
    int mask_start = nkt - 2;
    int mi = lane >> 3, r8 = lane & 7;

    for (int kt = 0; kt < nkt; kt++) {
        int st = kt & 1;
        if (kt + 1 < nkt) {
            LOADKV(kt + 1, st ^ 1);
            asm volatile("cp.async.wait_group 1;");
        } else {
            asm volatile("cp.async.wait_group 0;");
        }
        __syncthreads();

        unsigned kb = sb + ST0 + st * STSZ;
        unsigned vb = kb + VHOF;

        float sacc[8][4];
#pragma unroll
        for (int i = 0; i < 8; i++)
#pragma unroll
            for (int j = 0; j < 4; j++) sacc[i][j] = 0.f;

#pragma unroll
        for (int s = 0; s < 8; s++) {
            unsigned qh[4], ql[4];
            unsigned arow = warp * 16 + (mi & 1) * 8 + r8;
            unsigned ak = s * 16 + (mi >> 1) * 8;
            unsigned ao = sb + arow * ASTRB + ak * 2;
            ldsm_x4(qh, ao);
            ldsm_x4(ql, ao + AQ_LO);
#pragma unroll
            for (int j = 0; j < 4; j++) {
                unsigned kh4[4];
                unsigned krow = j * 16 + (mi >> 1) * 8 + r8;
                unsigned kk = s * 16 + (mi & 1) * 8;
                unsigned ko = kb + krow * ASTRB + kk * 2;
                ldsm_x4(kh4, ko);
                mma_f16(sacc[2 * j], qh, kh4);
                mma_f16(sacc[2 * j + 1], qh, kh4 + 2);
                mma_f16(sacc[2 * j], ql, kh4);
                mma_f16(sacc[2 * j + 1], ql, kh4 + 2);
            }
        }

        if (kt >= mask_start) {
            int colb = kt * 64 + 2 * (lane & 3);
#pragma unroll
            for (int nt = 0; nt < 8; nt++) {
                int c0 = colb + 8 * nt;
                if (c0 > qpos0)     sacc[nt][0] = -1e30f;
                if (c0 + 1 > qpos0) sacc[nt][1] = -1e30f;
                if (c0 > qpos0 + 8)     sacc[nt][2] = -1e30f;
                if (c0 + 1 > qpos0 + 8) sacc[nt][3] = -1e30f;
            }
        }

        float mx0 = -1e30f, mx1 = -1e30f;
#pragma unroll
        for (int nt = 0; nt < 8; nt++) {
            mx0 = fmaxf(mx0, fmaxf(sacc[nt][0], sacc[nt][1]));
            mx1 = fmaxf(mx1, fmaxf(sacc[nt][2], sacc[nt][3]));
        }
        mx0 = fmaxf(mx0, __shfl_xor_sync(0xffffffffu, mx0, 1));
        mx0 = fmaxf(mx0, __shfl_xor_sync(0xffffffffu, mx0, 2));
        mx1 = fmaxf(mx1, __shfl_xor_sync(0xffffffffu, mx1, 1));
        mx1 = fmaxf(mx1, __shfl_xor_sync(0xffffffffu, mx1, 2));
        float mn0 = fmaxf(mrow0, mx0), mn1 = fmaxf(mrow1, mx1);
        float corr0 = __expf(mrow0 - mn0), corr1 = __expf(mrow1 - mn1);
        float ls0 = 0.f, ls1 = 0.f;
#pragma unroll
        for (int nt = 0; nt < 8; nt++) {
            sacc[nt][0] = __expf(sacc[nt][0] - mn0);
            sacc[nt][1] = __expf(sacc[nt][1] - mn0);
            sacc[nt][2] = __expf(sacc[nt][2] - mn1);
            sacc[nt][3] = __expf(sacc[nt][3] - mn1);
            ls0 += sacc[nt][0] + sacc[nt][1];
            ls1 += sacc[nt][2] + sacc[nt][3];
        }
        ls0 += __shfl_xor_sync(0xffffffffu, ls0, 1);
        ls0 += __shfl_xor_sync(0xffffffffu, ls0, 2);
        ls1 += __shfl_xor_sync(0xffffffffu, ls1, 1);
        ls1 += __shfl_xor_sync(0xffffffffu, ls1, 2);
        lrow0 = lrow0 * corr0 + ls0;
        lrow1 = lrow1 * corr1 + ls1;
        mrow0 = mn0;
        mrow1 = mn1;
#pragma unroll
        for (int nt = 0; nt < 16; nt++) {
            O[nt][0] *= corr0; O[nt][1] *= corr0;
            O[nt][2] *= corr1; O[nt][3] *= corr1;
        }

        // ---- O += P V (single-term fp16: Ph * Vh) ----
#pragma unroll
        for (int u = 0; u < 4; u++) {
            unsigned pha[4];
            pha[0] = pack2h(sacc[2 * u][0], sacc[2 * u][1]);
            pha[1] = pack2h(sacc[2 * u][2], sacc[2 * u][3]);
            pha[2] = pack2h(sacc[2 * u + 1][0], sacc[2 * u + 1][1]);
            pha[3] = pack2h(sacc[2 * u + 1][2], sacc[2 * u + 1][3]);
#pragma unroll
            for (int t = 0; t < 8; t++) {
                unsigned vh4[4];
                unsigned vrow = u * 16 + (mi & 1) * 8 + r8;
                unsigned vdh = t * 16 + (mi >> 1) * 8;
                unsigned vo = vb + vrow * ASTRB + vdh * 2;
                ldsm_x4t(vh4, vo);
                mma_f16(O[2 * t], pha, vh4);
                mma_f16(O[2 * t + 1], pha, vh4 + 2);
            }
        }
        __syncthreads();
    }
#undef LOADKV

    float inv0 = 1.f / lrow0, inv1 = 1.f / lrow1;
    int b = bh >> 4, h = bh & 15;
    int r0 = qt * 128 + warp * 16 + (lane >> 2);
    int cbase = h * CDH + 2 * (lane & 3);
#pragma unroll
    for (int nt = 0; nt < 16; nt++) {
#pragma unroll
        for (int e = 0; e < 4; e++) {
            int row = (e < 2) ? r0 : r0 + 8;
            float val = O[nt][e] * ((e < 2) ? inv0 : inv1);
            int col = cbase + nt * 8 + (e & 1);
            size_t off = (size_t)(b * CN + row) * CDIM + col;
            unsigned short hh, ll;
            f16_split(val, hh, ll);
            g_attn_hi[off] = hh;
            g_attn_lo[off] = ll;
        }
    }
}

// ---------------- launch ----------------------------------------------------
extern "C" void kernel_launch(void* const* d_in, const int* in_sizes, int n_in,
                              void* d_out, int out_size) {
    const float* x      = (const float*)d_in[0];
    const float* past_k = (const float*)d_in[1];
    const float* past_v = (const float*)d_in[2];
    const float* w_qkv  = (const float*)d_in[4];
    const float* w_out  = (const float*)d_in[5];
    const float* ln_g   = (const float*)d_in[6];
    const float* ln_b   = (const float*)d_in[7];

    float* out  = (float*)d_out;                       // [2,1024,2048]
    float* kout = out + (size_t)CB * CN * CDIM;        // [2,16,2048,128]
    float* vout = kout + (size_t)CB * CH * CKV * CDH;  // [2,16,2048,128]

    cudaFuncSetAttribute(attn_mma_kernel,
                         cudaFuncAttributeMaxDynamicSharedMemorySize, SMEM_A3);
    cudaFuncSetAttribute(mma_gemm<NQKV, 1>,
                         cudaFuncAttributeMaxDynamicSharedMemorySize, SMEM_G);
    cudaFuncSetAttribute(mma_gemm<CDIM, 0>,
                         cudaFuncAttributeMaxDynamicSharedMemorySize, SMEM_G);

    // QKV GEMM at captured launch index 3; rope table precedes it (fused epilogue)
    ln_kernel<<<NTOK, 256>>>(x, ln_g, ln_b);
    transpose_split_kernel<0><<<dim3(NQKV / 32, CDIM / 32), dim3(32, 8)>>>(w_qkv);
    rope_table_kernel<<<512, 256>>>();

    mma_gemm<NQKV, 1><<<dim3(48, 16), 256, SMEM_G>>>(nullptr, kout, vout);

    transpose_split_kernel<1><<<dim3(CDIM / 32, CDIM / 32), dim3(32, 8)>>>(w_out);
    rope_k_past_kernel<<<(CB * CH * CPAST * 64) / 256, 256>>>(past_k, kout);
    split_v_past_kernel<<<(CB * CH * CPAST * 32) / 256, 256>>>(past_v, vout);

    attn_mma_kernel<<<256, 256, SMEM_A3>>>(kout, vout);

    mma_gemm<CDIM, 0><<<dim3(16, 16), 256, SMEM_G>>>(out, nullptr, nullptr);
}